// round 4
// baseline (speedup 1.0000x reference)
#include <cuda_runtime.h>
#include <math.h>

#define NN   131072
#define EE   262144
#define BBG  4096
#define HIDD 256
#define LLAY 4

// ---------------- scratch (device globals; no allocation) ----------------
__device__ float g_h[(size_t)NN * HIDD];     // node states        134 MB
__device__ float g_e[(size_t)EE * HIDD];     // edge embeddings    268 MB
__device__ float g_agg[(size_t)NN * HIDD];   // scatter-add target 134 MB
__device__ float g_u[(size_t)NN * HIDD];     // update GEMM out    134 MB
__device__ float g_gout[(size_t)BBG * 512];  // readout [B,512]
__device__ int   g_starts[BBG + 1];

// ---------------- generic 128x128x8 tiled SGEMM ----------------
// AMODE: 0 = dense A, K%8==0, rows 16B-aligned (vec4 loads)
//        1 = dense A, ragged K (scalar guarded loads; B rows guarded too)
//        2 = concat A: row i = [ g_h[src[i]] (256) | g_e[i] (256) ], K=512
// EPI:   0 = C[r*256+c] = relu(acc + bias[c])
//        1 = atomicAdd(&C[dst[r]*256+c], relu(acc + bias[c]))
template <int AMODE, int EPI>
__global__ __launch_bounds__(256, 2)
void gemm128(const float* __restrict__ A, int lda, int K,
             const float* __restrict__ Bw,
             const float* __restrict__ bias,
             float* __restrict__ C,
             const int* __restrict__ src,
             const int* __restrict__ dst)
{
    __shared__ float As[8][128];
    __shared__ float Bs[8][128];
    __shared__ int   s_src[128];
    __shared__ int   s_dst[128];

    const int tid  = threadIdx.x;
    const int row0 = blockIdx.y * 128;
    const int col0 = blockIdx.x * 128;

    const int aRow = tid >> 1;          // 0..127
    const int aCol = (tid & 1) << 2;    // 0 or 4
    const int bRow = tid >> 5;          // 0..7
    const int bCol = (tid & 31) << 2;   // 0..124

    if (AMODE == 2) {
        if (tid < 128) {
            s_src[tid] = src[row0 + tid];
            s_dst[tid] = dst[row0 + tid];
        }
        __syncthreads();
    }

    float acc[8][8];
#pragma unroll
    for (int i = 0; i < 8; i++)
#pragma unroll
        for (int j = 0; j < 8; j++) acc[i][j] = 0.f;

    const int tx = tid & 15;
    const int ty = tid >> 4;

    for (int kt = 0; kt < K; kt += 8) {
        // ---- A tile load ----
        float4 a4;
        if (AMODE == 0) {
            a4 = *(const float4*)(A + (size_t)(row0 + aRow) * lda + kt + aCol);
        } else if (AMODE == 1) {
            float t0 = 0.f, t1 = 0.f, t2 = 0.f, t3 = 0.f;
            const float* arow = A + (size_t)(row0 + aRow) * lda;
            int k0 = kt + aCol;
            if (k0 + 0 < K) t0 = arow[k0 + 0];
            if (k0 + 1 < K) t1 = arow[k0 + 1];
            if (k0 + 2 < K) t2 = arow[k0 + 2];
            if (k0 + 3 < K) t3 = arow[k0 + 3];
            a4 = make_float4(t0, t1, t2, t3);
        } else {
            int k0 = kt + aCol;
            const float* base;
            if (k0 < 256) base = g_h + (size_t)s_src[aRow] * 256 + k0;
            else          base = g_e + (size_t)(row0 + aRow) * 256 + (k0 - 256);
            a4 = *(const float4*)base;
        }
        As[aCol + 0][aRow] = a4.x;
        As[aCol + 1][aRow] = a4.y;
        As[aCol + 2][aRow] = a4.z;
        As[aCol + 3][aRow] = a4.w;

        // ---- B tile load (B is [K,256] row-major) ----
        {
            int kb = kt + bRow;
            float4 b4;
            if (AMODE == 1 && kb >= K) b4 = make_float4(0.f, 0.f, 0.f, 0.f);
            else b4 = *(const float4*)(Bw + (size_t)kb * 256 + col0 + bCol);
            *(float4*)&Bs[bRow][bCol] = b4;
        }

        __syncthreads();

#pragma unroll
        for (int kk = 0; kk < 8; kk++) {
            float ra[8], rb[8];
            *(float4*)&ra[0] = *(const float4*)&As[kk][ty * 8];
            *(float4*)&ra[4] = *(const float4*)&As[kk][ty * 8 + 4];
            *(float4*)&rb[0] = *(const float4*)&Bs[kk][tx * 8];
            *(float4*)&rb[4] = *(const float4*)&Bs[kk][tx * 8 + 4];
#pragma unroll
            for (int i = 0; i < 8; i++)
#pragma unroll
                for (int j = 0; j < 8; j++)
                    acc[i][j] = fmaf(ra[i], rb[j], acc[i][j]);
        }
        __syncthreads();
    }

    float bb[8];
#pragma unroll
    for (int j = 0; j < 8; j++) bb[j] = bias[col0 + tx * 8 + j];

    if (EPI == 0) {
#pragma unroll
        for (int i = 0; i < 8; i++) {
            int r = row0 + ty * 8 + i;
            float4 o0, o1;
            o0.x = fmaxf(acc[i][0] + bb[0], 0.f);
            o0.y = fmaxf(acc[i][1] + bb[1], 0.f);
            o0.z = fmaxf(acc[i][2] + bb[2], 0.f);
            o0.w = fmaxf(acc[i][3] + bb[3], 0.f);
            o1.x = fmaxf(acc[i][4] + bb[4], 0.f);
            o1.y = fmaxf(acc[i][5] + bb[5], 0.f);
            o1.z = fmaxf(acc[i][6] + bb[6], 0.f);
            o1.w = fmaxf(acc[i][7] + bb[7], 0.f);
            float* cp = C + (size_t)r * 256 + col0 + tx * 8;
            *(float4*)(cp)     = o0;
            *(float4*)(cp + 4) = o1;
        }
    } else {
#pragma unroll
        for (int i = 0; i < 8; i++) {
            int d = s_dst[ty * 8 + i];
            float* base = C + (size_t)d * 256 + col0 + tx * 8;
#pragma unroll
            for (int j = 0; j < 8; j++) {
                float v = fmaxf(acc[i][j] + bb[j], 0.f);
                atomicAdd(base + j, v);
            }
        }
    }
}

// ---------------- LayerNorm: h = LN(h + u, g, b), warp per row ----------------
__global__ void ln_kernel(const float* __restrict__ u,
                          const float* __restrict__ lg,
                          const float* __restrict__ lb)
{
    int row  = blockIdx.x * 8 + (threadIdx.x >> 5);
    int lane = threadIdx.x & 31;
    float*       hrow = g_h + (size_t)row * 256;
    const float* urow = u   + (size_t)row * 256;

    float x[8];
    float4 h0 = *(const float4*)(hrow + lane * 4);
    float4 h1 = *(const float4*)(hrow + 128 + lane * 4);
    float4 u0 = *(const float4*)(urow + lane * 4);
    float4 u1 = *(const float4*)(urow + 128 + lane * 4);
    x[0] = h0.x + u0.x; x[1] = h0.y + u0.y; x[2] = h0.z + u0.z; x[3] = h0.w + u0.w;
    x[4] = h1.x + u1.x; x[5] = h1.y + u1.y; x[6] = h1.z + u1.z; x[7] = h1.w + u1.w;

    float s = 0.f, q = 0.f;
#pragma unroll
    for (int j = 0; j < 8; j++) { s += x[j]; q += x[j] * x[j]; }
#pragma unroll
    for (int o = 16; o > 0; o >>= 1) {
        s += __shfl_xor_sync(0xFFFFFFFFu, s, o);
        q += __shfl_xor_sync(0xFFFFFFFFu, q, o);
    }
    float mu  = s * (1.f / 256.f);
    float var = q * (1.f / 256.f) - mu * mu;
    float rs  = rsqrtf(var + 1e-5f);

    float4 g0 = *(const float4*)(lg + lane * 4);
    float4 g1 = *(const float4*)(lg + 128 + lane * 4);
    float4 b0 = *(const float4*)(lb + lane * 4);
    float4 b1 = *(const float4*)(lb + 128 + lane * 4);

    float4 y0, y1;
    y0.x = (x[0] - mu) * rs * g0.x + b0.x;
    y0.y = (x[1] - mu) * rs * g0.y + b0.y;
    y0.z = (x[2] - mu) * rs * g0.z + b0.z;
    y0.w = (x[3] - mu) * rs * g0.w + b0.w;
    y1.x = (x[4] - mu) * rs * g1.x + b1.x;
    y1.y = (x[5] - mu) * rs * g1.y + b1.y;
    y1.z = (x[6] - mu) * rs * g1.z + b1.z;
    y1.w = (x[7] - mu) * rs * g1.w + b1.w;
    *(float4*)(hrow + lane * 4)       = y0;
    *(float4*)(hrow + 128 + lane * 4) = y1;
}

// ---------------- segment starts from sorted b ----------------
__global__ void seg_starts(const int* __restrict__ b)
{
    int i = blockIdx.x * blockDim.x + threadIdx.x;
    if (i >= NN) return;
    int cur = b[i];
    if (i == 0) {
        for (int g = 0; g <= cur; g++) g_starts[g] = 0;
    } else {
        int prev = b[i - 1];
        if (prev != cur)
            for (int g = prev + 1; g <= cur; g++) g_starts[g] = i;
    }
    if (i == NN - 1)
        for (int g = cur + 1; g <= BBG; g++) g_starts[g] = NN;
}

// ---------------- readout: mean || max per graph ----------------
__global__ void readout_kernel(void)
{
    int g = blockIdx.x;
    int s = g_starts[g], en = g_starts[g + 1];
    int c = threadIdx.x;
    float sum = 0.f, mx = -INFINITY;
    for (int r = s; r < en; r++) {
        float v = g_h[(size_t)r * 256 + c];
        sum += v;
        mx = fmaxf(mx, v);
    }
    int   cnt   = en - s;
    float denom = (cnt > 0) ? (float)cnt : 1.f;
    g_gout[(size_t)g * 512 + c]       = sum / denom;
    g_gout[(size_t)g * 512 + 256 + c] = (cnt > 0) ? mx : 0.f;
}

// ---------------- FiLM + predictor, 8 graphs per block ----------------
__global__ __launch_bounds__(256)
void film_pred(const float* __restrict__ ctx, const int* __restrict__ pid,
               const float* __restrict__ gW1, const float* __restrict__ gb1,
               const float* __restrict__ glng, const float* __restrict__ glnb,
               const float* __restrict__ gW2, const float* __restrict__ gb2,
               const float* __restrict__ bW1, const float* __restrict__ bb1,
               const float* __restrict__ blng, const float* __restrict__ blnb,
               const float* __restrict__ bW2, const float* __restrict__ bb2,
               const float* __restrict__ pW1, const float* __restrict__ pb1,
               const float* __restrict__ pW2, const float* __restrict__ pb2,
               float* __restrict__ out)
{
    __shared__ float s_c[8][128];
    __shared__ float s_t[8][256];
    __shared__ float s_hmod[8][512];

    int tid = threadIdx.x;
    int g0  = blockIdx.x * 8;

    for (int i = tid; i < 8 * 128; i += 256) {
        int r = i >> 7, k = i & 127;
        s_c[r][k] = ctx[(size_t)pid[g0 + r] * 128 + k];
    }
    __syncthreads();

#pragma unroll
    for (int net = 0; net < 2; net++) {
        const float* W1 = net ? bW1 : gW1;
        const float* B1 = net ? bb1 : gb1;
        const float* LG = net ? blng : glng;
        const float* LB = net ? blnb : glnb;
        const float* W2 = net ? bW2 : gW2;
        const float* B2 = net ? bb2 : gb2;

        // t1 = c @ W1 + B1   (col = tid)
        float a1[8];
#pragma unroll
        for (int r = 0; r < 8; r++) a1[r] = B1[tid];
        for (int k = 0; k < 128; k++) {
            float w = W1[k * 256 + tid];
#pragma unroll
            for (int r = 0; r < 8; r++) a1[r] += s_c[r][k] * w;
        }
#pragma unroll
        for (int r = 0; r < 8; r++) s_t[r][tid] = a1[r];
        __syncthreads();

        // LN + relu per row (warp w handles row w)
        {
            int r = tid >> 5, lane = tid & 31;
            float x[8], s = 0.f, q = 0.f;
#pragma unroll
            for (int j = 0; j < 8; j++) {
                x[j] = s_t[r][lane + 32 * j];
                s += x[j]; q += x[j] * x[j];
            }
#pragma unroll
            for (int o = 16; o > 0; o >>= 1) {
                s += __shfl_xor_sync(0xFFFFFFFFu, s, o);
                q += __shfl_xor_sync(0xFFFFFFFFu, q, o);
            }
            float mu  = s * (1.f / 256.f);
            float var = q * (1.f / 256.f) - mu * mu;
            float rs  = rsqrtf(var + 1e-5f);
#pragma unroll
            for (int j = 0; j < 8; j++) {
                int c = lane + 32 * j;
                float y = (x[j] - mu) * rs * LG[c] + LB[c];
                s_t[r][c] = fmaxf(y, 0.f);
            }
        }
        __syncthreads();

        // out512 = t1 @ W2 + B2; fuse into hmod
        float a20[8], a21[8];
#pragma unroll
        for (int r = 0; r < 8; r++) { a20[r] = 0.f; a21[r] = 0.f; }
        for (int k = 0; k < 256; k++) {
            float w0 = W2[k * 512 + tid];
            float w1 = W2[k * 512 + tid + 256];
#pragma unroll
            for (int r = 0; r < 8; r++) {
                float t = s_t[r][k];
                a20[r] += t * w0;
                a21[r] += t * w1;
            }
        }
        float bc0 = B2[tid], bc1 = B2[tid + 256];
        if (net == 0) {
#pragma unroll
            for (int r = 0; r < 8; r++) {
                s_hmod[r][tid]       = (a20[r] + bc0) * g_gout[(size_t)(g0 + r) * 512 + tid];
                s_hmod[r][tid + 256] = (a21[r] + bc1) * g_gout[(size_t)(g0 + r) * 512 + tid + 256];
            }
        } else {
#pragma unroll
            for (int r = 0; r < 8; r++) {
                s_hmod[r][tid]       += a20[r] + bc0;
                s_hmod[r][tid + 256] += a21[r] + bc1;
            }
        }
        __syncthreads();
    }

    // predictor layer 1: z = relu(hmod @ pW1 + pb1)
    float az[8];
#pragma unroll
    for (int r = 0; r < 8; r++) az[r] = pb1[tid];
    for (int k = 0; k < 512; k++) {
        float w = pW1[k * 256 + tid];
#pragma unroll
        for (int r = 0; r < 8; r++) az[r] += s_hmod[r][k] * w;
    }
#pragma unroll
    for (int r = 0; r < 8; r++) s_t[r][tid] = fmaxf(az[r], 0.f);
    __syncthreads();

    // final: out = z @ pW2 + pb2  (warp w reduces row w)
    {
        int r = tid >> 5, lane = tid & 31;
        float p = 0.f;
#pragma unroll
        for (int j = 0; j < 8; j++) {
            int c = lane + 32 * j;
            p += s_t[r][c] * pW2[c];
        }
#pragma unroll
        for (int o = 16; o > 0; o >>= 1) p += __shfl_xor_sync(0xFFFFFFFFu, p, o);
        if (lane == 0) out[g0 + r] = p + pb2[0];
    }
}

// ---------------- host launcher ----------------
extern "C" void kernel_launch(void* const* d_in, const int* in_sizes, int n_in,
                              void* d_out, int out_size)
{
    (void)in_sizes; (void)n_in; (void)out_size;

    const float* nf   = (const float*)d_in[0];
    const int*   ei   = (const int*)  d_in[1];
    const float* ef   = (const float*)d_in[2];
    const int*   bseg = (const int*)  d_in[3];
    const int*   pid  = (const int*)  d_in[4];
    const float* Wn   = (const float*)d_in[5];
    const float* bn   = (const float*)d_in[6];
    const float* We   = (const float*)d_in[7];
    const float* be   = (const float*)d_in[8];
    const float* Wm   = (const float*)d_in[9];
    const float* bm   = (const float*)d_in[10];
    const float* Wu   = (const float*)d_in[11];
    const float* bu   = (const float*)d_in[12];
    const float* lng  = (const float*)d_in[13];
    const float* lnb  = (const float*)d_in[14];
    const float* ctx  = (const float*)d_in[15];
    const float* gW1  = (const float*)d_in[16];
    const float* gb1  = (const float*)d_in[17];
    const float* glng = (const float*)d_in[18];
    const float* glnb = (const float*)d_in[19];
    const float* gW2  = (const float*)d_in[20];
    const float* gb2  = (const float*)d_in[21];
    const float* bW1  = (const float*)d_in[22];
    const float* bb1  = (const float*)d_in[23];
    const float* blng = (const float*)d_in[24];
    const float* blnb = (const float*)d_in[25];
    const float* bW2  = (const float*)d_in[26];
    const float* bb2  = (const float*)d_in[27];
    const float* pW1  = (const float*)d_in[28];
    const float* pb1  = (const float*)d_in[29];
    const float* pW2  = (const float*)d_in[30];
    const float* pb2  = (const float*)d_in[31];
    float* out = (float*)d_out;

    const int* src = ei;
    const int* dst = ei + EE;

    float *h_ptr, *e_ptr, *agg_ptr, *u_ptr;
    cudaGetSymbolAddress((void**)&h_ptr,   g_h);
    cudaGetSymbolAddress((void**)&e_ptr,   g_e);
    cudaGetSymbolAddress((void**)&agg_ptr, g_agg);
    cudaGetSymbolAddress((void**)&u_ptr,   g_u);

    dim3 thr(256);

    // input embeddings
    gemm128<1, 0><<<dim3(2, NN / 128), thr>>>(nf, 69, 69, Wn, bn, h_ptr, nullptr, nullptr);
    gemm128<1, 0><<<dim3(2, EE / 128), thr>>>(ef, 9, 9, We, be, e_ptr, nullptr, nullptr);

    // MPNN layers
    for (int l = 0; l < LLAY; l++) {
        cudaMemsetAsync(agg_ptr, 0, (size_t)NN * HIDD * sizeof(float), 0);
        gemm128<2, 1><<<dim3(2, EE / 128), thr>>>(
            nullptr, 512, 512, Wm + (size_t)l * 512 * 256, bm + (size_t)l * 256,
            agg_ptr, src, dst);
        gemm128<0, 0><<<dim3(2, NN / 128), thr>>>(
            agg_ptr, 256, 256, Wu + (size_t)l * 256 * 256, bu + (size_t)l * 256,
            u_ptr, nullptr, nullptr);
        ln_kernel<<<NN / 8, 256>>>(u_ptr, lng + (size_t)l * 256, lnb + (size_t)l * 256);
    }

    // readout + FiLM + predictor
    seg_starts<<<NN / 256, 256>>>(bseg);
    readout_kernel<<<BBG, 256>>>();
    film_pred<<<BBG / 8, 256>>>(ctx, pid,
                                gW1, gb1, glng, glnb, gW2, gb2,
                                bW1, bb1, blng, blnb, bW2, bb2,
                                pW1, pb1, pW2, pb2, out);
}

// round 5
// speedup vs baseline: 1.3752x; 1.3752x over previous
#include <cuda_runtime.h>
#include <math.h>

#define NN   131072
#define EE   262144
#define BBG  4096
#define HIDD 256
#define LLAY 4

// ---------------- scratch (device globals; no allocation) ----------------
__device__ float g_h[(size_t)NN * HIDD];     // node states        134 MB
__device__ float g_e[(size_t)EE * HIDD];     // edge embeddings    268 MB
__device__ float g_agg[(size_t)NN * HIDD];   // scatter-add target 134 MB
__device__ float g_u[(size_t)NN * HIDD];     // update GEMM out    134 MB
__device__ float g_gout[(size_t)BBG * 512];  // readout [B,512]
__device__ int   g_starts[BBG + 1];

// ---------------- generic 128x128x8 tiled SGEMM (double-buffered) ----------------
// AMODE: 0 = dense A, K%8==0, rows 16B-aligned (vec4 loads)
//        1 = dense A, ragged K (scalar guarded loads; B rows guarded too)
//        2 = concat A: row i = [ g_h[src[i]] (256) | g_e[i] (256) ], K=512
// EPI:   0 = C[r*256+c] = relu(acc + bias[c])
//        1 = atomicAdd(&C[dst[r]*256+c], relu(acc + bias[c]))
//
// Microtile mapping (conflict-free): thread (tx,ty), tx=tid&15, ty=tid>>4
//   rows:  ty*4 + {0..3}  and  64 + ty*4 + {0..3}
//   cols:  tx*4 + {0..3}  and  64 + tx*4 + {0..3}
template <int AMODE, int EPI>
__global__ __launch_bounds__(256, 2)
void gemm128(const float* __restrict__ A, int lda, int K,
             const float* __restrict__ Bw,
             const float* __restrict__ bias,
             float* __restrict__ C,
             const int* __restrict__ src,
             const int* __restrict__ dst)
{
    __shared__ float As[2][8][128];
    __shared__ float Bs[2][8][128];
    __shared__ int   s_src[128];
    __shared__ int   s_dst[128];

    const int tid  = threadIdx.x;
    const int row0 = blockIdx.y * 128;
    const int col0 = blockIdx.x * 128;

    const int aRow = tid >> 1;          // 0..127
    const int aCol = (tid & 1) << 2;    // 0 or 4
    const int bRow = tid >> 5;          // 0..7
    const int bCol = (tid & 31) << 2;   // 0..124

    if (AMODE == 2) {
        if (tid < 128) {
            s_src[tid] = src[row0 + tid];
            s_dst[tid] = dst[row0 + tid];
        }
        __syncthreads();
    }

    auto load_a = [&](int kt) -> float4 {
        if (AMODE == 0) {
            return *(const float4*)(A + (size_t)(row0 + aRow) * lda + kt + aCol);
        } else if (AMODE == 1) {
            float t0 = 0.f, t1 = 0.f, t2 = 0.f, t3 = 0.f;
            const float* arow = A + (size_t)(row0 + aRow) * lda;
            int k0 = kt + aCol;
            if (k0 + 0 < K) t0 = arow[k0 + 0];
            if (k0 + 1 < K) t1 = arow[k0 + 1];
            if (k0 + 2 < K) t2 = arow[k0 + 2];
            if (k0 + 3 < K) t3 = arow[k0 + 3];
            return make_float4(t0, t1, t2, t3);
        } else {
            int k0 = kt + aCol;
            const float* base = (k0 < 256)
                ? (g_h + (size_t)s_src[aRow] * 256 + k0)
                : (g_e + (size_t)(row0 + aRow) * 256 + (k0 - 256));
            return *(const float4*)base;
        }
    };

    auto load_b = [&](int kt) -> float4 {
        int kb = kt + bRow;
        if (AMODE == 1 && kb >= K) return make_float4(0.f, 0.f, 0.f, 0.f);
        return *(const float4*)(Bw + (size_t)kb * 256 + col0 + bCol);
    };

    auto store_tile = [&](int p, float4 a4, float4 b4) {
        As[p][aCol + 0][aRow] = a4.x;
        As[p][aCol + 1][aRow] = a4.y;
        As[p][aCol + 2][aRow] = a4.z;
        As[p][aCol + 3][aRow] = a4.w;
        *(float4*)&Bs[p][bRow][bCol] = b4;
    };

    float acc[8][8];
#pragma unroll
    for (int i = 0; i < 8; i++)
#pragma unroll
        for (int j = 0; j < 8; j++) acc[i][j] = 0.f;

    const int tx = tid & 15;
    const int ty = tid >> 4;

    auto compute = [&](int p) {
#pragma unroll
        for (int kk = 0; kk < 8; kk++) {
            float ra[8], rb[8];
            *(float4*)&ra[0] = *(const float4*)&As[p][kk][ty * 4];
            *(float4*)&ra[4] = *(const float4*)&As[p][kk][64 + ty * 4];
            *(float4*)&rb[0] = *(const float4*)&Bs[p][kk][tx * 4];
            *(float4*)&rb[4] = *(const float4*)&Bs[p][kk][64 + tx * 4];
#pragma unroll
            for (int i = 0; i < 8; i++)
#pragma unroll
                for (int j = 0; j < 8; j++)
                    acc[i][j] = fmaf(ra[i], rb[j], acc[i][j]);
        }
    };

    // prologue: fill buffer 0
    store_tile(0, load_a(0), load_b(0));
    __syncthreads();

    int p = 0;
    for (int kt = 8; kt < K; kt += 8) {
        float4 a4 = load_a(kt);     // prefetch next tile (global)
        float4 b4 = load_b(kt);
        compute(p);                  // compute on current buffer
        store_tile(p ^ 1, a4, b4);   // fill other buffer
        __syncthreads();
        p ^= 1;
    }
    compute(p);                      // last tile

    // epilogue
    float bb[8];
#pragma unroll
    for (int j = 0; j < 4; j++) {
        bb[j]     = bias[col0 + tx * 4 + j];
        bb[4 + j] = bias[col0 + 64 + tx * 4 + j];
    }

    if (EPI == 0) {
#pragma unroll
        for (int i = 0; i < 8; i++) {
            int lrow = (i < 4) ? (ty * 4 + i) : (64 + ty * 4 + (i - 4));
            float* cp = C + (size_t)(row0 + lrow) * 256 + col0;
            float4 o0, o1;
            o0.x = fmaxf(acc[i][0] + bb[0], 0.f);
            o0.y = fmaxf(acc[i][1] + bb[1], 0.f);
            o0.z = fmaxf(acc[i][2] + bb[2], 0.f);
            o0.w = fmaxf(acc[i][3] + bb[3], 0.f);
            o1.x = fmaxf(acc[i][4] + bb[4], 0.f);
            o1.y = fmaxf(acc[i][5] + bb[5], 0.f);
            o1.z = fmaxf(acc[i][6] + bb[6], 0.f);
            o1.w = fmaxf(acc[i][7] + bb[7], 0.f);
            *(float4*)(cp + tx * 4)      = o0;
            *(float4*)(cp + 64 + tx * 4) = o1;
        }
    } else {
#pragma unroll
        for (int i = 0; i < 8; i++) {
            int lrow = (i < 4) ? (ty * 4 + i) : (64 + ty * 4 + (i - 4));
            int d = s_dst[lrow];
            float* base = C + (size_t)d * 256 + col0;
#pragma unroll
            for (int j = 0; j < 4; j++) {
                atomicAdd(base + tx * 4 + j,      fmaxf(acc[i][j]     + bb[j],     0.f));
                atomicAdd(base + 64 + tx * 4 + j, fmaxf(acc[i][4 + j] + bb[4 + j], 0.f));
            }
        }
    }
}

// ---------------- LayerNorm: h = LN(h + u, g, b), warp per row ----------------
__global__ void ln_kernel(const float* __restrict__ u,
                          const float* __restrict__ lg,
                          const float* __restrict__ lb)
{
    int row  = blockIdx.x * 8 + (threadIdx.x >> 5);
    int lane = threadIdx.x & 31;
    float*       hrow = g_h + (size_t)row * 256;
    const float* urow = u   + (size_t)row * 256;

    float x[8];
    float4 h0 = *(const float4*)(hrow + lane * 4);
    float4 h1 = *(const float4*)(hrow + 128 + lane * 4);
    float4 u0 = *(const float4*)(urow + lane * 4);
    float4 u1 = *(const float4*)(urow + 128 + lane * 4);
    x[0] = h0.x + u0.x; x[1] = h0.y + u0.y; x[2] = h0.z + u0.z; x[3] = h0.w + u0.w;
    x[4] = h1.x + u1.x; x[5] = h1.y + u1.y; x[6] = h1.z + u1.z; x[7] = h1.w + u1.w;

    float s = 0.f, q = 0.f;
#pragma unroll
    for (int j = 0; j < 8; j++) { s += x[j]; q += x[j] * x[j]; }
#pragma unroll
    for (int o = 16; o > 0; o >>= 1) {
        s += __shfl_xor_sync(0xFFFFFFFFu, s, o);
        q += __shfl_xor_sync(0xFFFFFFFFu, q, o);
    }
    float mu  = s * (1.f / 256.f);
    float var = q * (1.f / 256.f) - mu * mu;
    float rs  = rsqrtf(var + 1e-5f);

    float4 g0 = *(const float4*)(lg + lane * 4);
    float4 g1 = *(const float4*)(lg + 128 + lane * 4);
    float4 b0 = *(const float4*)(lb + lane * 4);
    float4 b1 = *(const float4*)(lb + 128 + lane * 4);

    float4 y0, y1;
    y0.x = (x[0] - mu) * rs * g0.x + b0.x;
    y0.y = (x[1] - mu) * rs * g0.y + b0.y;
    y0.z = (x[2] - mu) * rs * g0.z + b0.z;
    y0.w = (x[3] - mu) * rs * g0.w + b0.w;
    y1.x = (x[4] - mu) * rs * g1.x + b1.x;
    y1.y = (x[5] - mu) * rs * g1.y + b1.y;
    y1.z = (x[6] - mu) * rs * g1.z + b1.z;
    y1.w = (x[7] - mu) * rs * g1.w + b1.w;
    *(float4*)(hrow + lane * 4)       = y0;
    *(float4*)(hrow + 128 + lane * 4) = y1;
}

// ---------------- segment starts from sorted b ----------------
__global__ void seg_starts(const int* __restrict__ b)
{
    int i = blockIdx.x * blockDim.x + threadIdx.x;
    if (i >= NN) return;
    int cur = b[i];
    if (i == 0) {
        for (int g = 0; g <= cur; g++) g_starts[g] = 0;
    } else {
        int prev = b[i - 1];
        if (prev != cur)
            for (int g = prev + 1; g <= cur; g++) g_starts[g] = i;
    }
    if (i == NN - 1)
        for (int g = cur + 1; g <= BBG; g++) g_starts[g] = NN;
}

// ---------------- readout: mean || max per graph ----------------
__global__ void readout_kernel(void)
{
    int g = blockIdx.x;
    int s = g_starts[g], en = g_starts[g + 1];
    int c = threadIdx.x;
    float sum = 0.f, mx = -INFINITY;
    for (int r = s; r < en; r++) {
        float v = g_h[(size_t)r * 256 + c];
        sum += v;
        mx = fmaxf(mx, v);
    }
    int   cnt   = en - s;
    float denom = (cnt > 0) ? (float)cnt : 1.f;
    g_gout[(size_t)g * 512 + c]       = sum / denom;
    g_gout[(size_t)g * 512 + 256 + c] = (cnt > 0) ? mx : 0.f;
}

// ---------------- FiLM + predictor, 8 graphs per block ----------------
__global__ __launch_bounds__(256)
void film_pred(const float* __restrict__ ctx, const int* __restrict__ pid,
               const float* __restrict__ gW1, const float* __restrict__ gb1,
               const float* __restrict__ glng, const float* __restrict__ glnb,
               const float* __restrict__ gW2, const float* __restrict__ gb2,
               const float* __restrict__ bW1, const float* __restrict__ bb1,
               const float* __restrict__ blng, const float* __restrict__ blnb,
               const float* __restrict__ bW2, const float* __restrict__ bb2,
               const float* __restrict__ pW1, const float* __restrict__ pb1,
               const float* __restrict__ pW2, const float* __restrict__ pb2,
               float* __restrict__ out)
{
    __shared__ float s_c[8][128];
    __shared__ float s_t[8][256];
    __shared__ float s_hmod[8][512];

    int tid = threadIdx.x;
    int g0  = blockIdx.x * 8;

    for (int i = tid; i < 8 * 128; i += 256) {
        int r = i >> 7, k = i & 127;
        s_c[r][k] = ctx[(size_t)pid[g0 + r] * 128 + k];
    }
    __syncthreads();

#pragma unroll
    for (int net = 0; net < 2; net++) {
        const float* W1 = net ? bW1 : gW1;
        const float* B1 = net ? bb1 : gb1;
        const float* LG = net ? blng : glng;
        const float* LB = net ? blnb : glnb;
        const float* W2 = net ? bW2 : gW2;
        const float* B2 = net ? bb2 : gb2;

        // t1 = c @ W1 + B1   (col = tid)
        float a1[8];
#pragma unroll
        for (int r = 0; r < 8; r++) a1[r] = B1[tid];
        for (int k = 0; k < 128; k++) {
            float w = W1[k * 256 + tid];
#pragma unroll
            for (int r = 0; r < 8; r++) a1[r] += s_c[r][k] * w;
        }
#pragma unroll
        for (int r = 0; r < 8; r++) s_t[r][tid] = a1[r];
        __syncthreads();

        // LN + relu per row (warp w handles row w)
        {
            int r = tid >> 5, lane = tid & 31;
            float x[8], s = 0.f, q = 0.f;
#pragma unroll
            for (int j = 0; j < 8; j++) {
                x[j] = s_t[r][lane + 32 * j];
                s += x[j]; q += x[j] * x[j];
            }
#pragma unroll
            for (int o = 16; o > 0; o >>= 1) {
                s += __shfl_xor_sync(0xFFFFFFFFu, s, o);
                q += __shfl_xor_sync(0xFFFFFFFFu, q, o);
            }
            float mu  = s * (1.f / 256.f);
            float var = q * (1.f / 256.f) - mu * mu;
            float rs  = rsqrtf(var + 1e-5f);
#pragma unroll
            for (int j = 0; j < 8; j++) {
                int c = lane + 32 * j;
                float y = (x[j] - mu) * rs * LG[c] + LB[c];
                s_t[r][c] = fmaxf(y, 0.f);
            }
        }
        __syncthreads();

        // out512 = t1 @ W2 + B2; fuse into hmod
        float a20[8], a21[8];
#pragma unroll
        for (int r = 0; r < 8; r++) { a20[r] = 0.f; a21[r] = 0.f; }
        for (int k = 0; k < 256; k++) {
            float w0 = W2[k * 512 + tid];
            float w1 = W2[k * 512 + tid + 256];
#pragma unroll
            for (int r = 0; r < 8; r++) {
                float t = s_t[r][k];
                a20[r] += t * w0;
                a21[r] += t * w1;
            }
        }
        float bc0 = B2[tid], bc1 = B2[tid + 256];
        if (net == 0) {
#pragma unroll
            for (int r = 0; r < 8; r++) {
                s_hmod[r][tid]       = (a20[r] + bc0) * g_gout[(size_t)(g0 + r) * 512 + tid];
                s_hmod[r][tid + 256] = (a21[r] + bc1) * g_gout[(size_t)(g0 + r) * 512 + tid + 256];
            }
        } else {
#pragma unroll
            for (int r = 0; r < 8; r++) {
                s_hmod[r][tid]       += a20[r] + bc0;
                s_hmod[r][tid + 256] += a21[r] + bc1;
            }
        }
        __syncthreads();
    }

    // predictor layer 1: z = relu(hmod @ pW1 + pb1)
    float az[8];
#pragma unroll
    for (int r = 0; r < 8; r++) az[r] = pb1[tid];
    for (int k = 0; k < 512; k++) {
        float w = pW1[k * 256 + tid];
#pragma unroll
        for (int r = 0; r < 8; r++) az[r] += s_hmod[r][k] * w;
    }
#pragma unroll
    for (int r = 0; r < 8; r++) s_t[r][tid] = fmaxf(az[r], 0.f);
    __syncthreads();

    // final: out = z @ pW2 + pb2  (warp w reduces row w)
    {
        int r = tid >> 5, lane = tid & 31;
        float p = 0.f;
#pragma unroll
        for (int j = 0; j < 8; j++) {
            int c = lane + 32 * j;
            p += s_t[r][c] * pW2[c];
        }
#pragma unroll
        for (int o = 16; o > 0; o >>= 1) p += __shfl_xor_sync(0xFFFFFFFFu, p, o);
        if (lane == 0) out[g0 + r] = p + pb2[0];
    }
}

// ---------------- host launcher ----------------
extern "C" void kernel_launch(void* const* d_in, const int* in_sizes, int n_in,
                              void* d_out, int out_size)
{
    (void)in_sizes; (void)n_in; (void)out_size;

    const float* nf   = (const float*)d_in[0];
    const int*   ei   = (const int*)  d_in[1];
    const float* ef   = (const float*)d_in[2];
    const int*   bseg = (const int*)  d_in[3];
    const int*   pid  = (const int*)  d_in[4];
    const float* Wn   = (const float*)d_in[5];
    const float* bn   = (const float*)d_in[6];
    const float* We   = (const float*)d_in[7];
    const float* be   = (const float*)d_in[8];
    const float* Wm   = (const float*)d_in[9];
    const float* bm   = (const float*)d_in[10];
    const float* Wu   = (const float*)d_in[11];
    const float* bu   = (const float*)d_in[12];
    const float* lng  = (const float*)d_in[13];
    const float* lnb  = (const float*)d_in[14];
    const float* ctx  = (const float*)d_in[15];
    const float* gW1  = (const float*)d_in[16];
    const float* gb1  = (const float*)d_in[17];
    const float* glng = (const float*)d_in[18];
    const float* glnb = (const float*)d_in[19];
    const float* gW2  = (const float*)d_in[20];
    const float* gb2  = (const float*)d_in[21];
    const float* bW1  = (const float*)d_in[22];
    const float* bb1  = (const float*)d_in[23];
    const float* blng = (const float*)d_in[24];
    const float* blnb = (const float*)d_in[25];
    const float* bW2  = (const float*)d_in[26];
    const float* bb2  = (const float*)d_in[27];
    const float* pW1  = (const float*)d_in[28];
    const float* pb1  = (const float*)d_in[29];
    const float* pW2  = (const float*)d_in[30];
    const float* pb2  = (const float*)d_in[31];
    float* out = (float*)d_out;

    const int* src = ei;
    const int* dst = ei + EE;

    float *h_ptr, *e_ptr, *agg_ptr, *u_ptr;
    cudaGetSymbolAddress((void**)&h_ptr,   g_h);
    cudaGetSymbolAddress((void**)&e_ptr,   g_e);
    cudaGetSymbolAddress((void**)&agg_ptr, g_agg);
    cudaGetSymbolAddress((void**)&u_ptr,   g_u);

    dim3 thr(256);

    // input embeddings
    gemm128<1, 0><<<dim3(2, NN / 128), thr>>>(nf, 69, 69, Wn, bn, h_ptr, nullptr, nullptr);
    gemm128<1, 0><<<dim3(2, EE / 128), thr>>>(ef, 9, 9, We, be, e_ptr, nullptr, nullptr);

    // MPNN layers
    for (int l = 0; l < LLAY; l++) {
        cudaMemsetAsync(agg_ptr, 0, (size_t)NN * HIDD * sizeof(float), 0);
        gemm128<2, 1><<<dim3(2, EE / 128), thr>>>(
            nullptr, 512, 512, Wm + (size_t)l * 512 * 256, bm + (size_t)l * 256,
            agg_ptr, src, dst);
        gemm128<0, 0><<<dim3(2, NN / 128), thr>>>(
            agg_ptr, 256, 256, Wu + (size_t)l * 256 * 256, bu + (size_t)l * 256,
            u_ptr, nullptr, nullptr);
        ln_kernel<<<NN / 8, 256>>>(u_ptr, lng + (size_t)l * 256, lnb + (size_t)l * 256);
    }

    // readout + FiLM + predictor
    seg_starts<<<NN / 256, 256>>>(bseg);
    readout_kernel<<<BBG, 256>>>();
    film_pred<<<BBG / 8, 256>>>(ctx, pid,
                                gW1, gb1, glng, glnb, gW2, gb2,
                                bW1, bb1, blng, blnb, bW2, bb2,
                                pW1, pb1, pW2, pb2, out);
}

// round 6
// speedup vs baseline: 1.6428x; 1.1945x over previous
#include <cuda_runtime.h>
#include <math.h>

#define NN   131072
#define EE   262144
#define BBG  4096
#define HIDD 256
#define LLAY 4

// ---------------- scratch (device globals; no allocation) ----------------
__device__ float g_h[(size_t)NN * HIDD];     // node states
__device__ float g_e[(size_t)EE * HIDD];     // edge embeddings
__device__ float g_agg[(size_t)NN * HIDD];   // scatter-add target
__device__ float g_u[(size_t)NN * HIDD];     // update GEMM out
__device__ float g_t[(size_t)NN * HIDD];     // per-node message part (h @ Wm_top)
__device__ float g_gout[(size_t)BBG * 512];  // readout [B,512]
__device__ int   g_starts[BBG + 1];

// packed dual-fp32 helpers (sm_103a)
#define DUP2(d, f)   asm("mov.b64 %0, {%1, %1};" : "=l"(d) : "f"(f))
#define FMA2(c, a, b) asm("fma.rn.f32x2 %0, %1, %2, %0;" : "+l"(c) : "l"(a), "l"(b))
#define UNPK2(lo, hi, v) asm("mov.b64 {%0, %1}, %2;" : "=f"(lo), "=f"(hi) : "l"(v))

// ---------------- generic 128x128x8 tiled SGEMM (double-buffered, f32x2) ----------------
// AMODE: 0 = dense A, K%8==0, rows 16B-aligned (vec4 loads)
//        1 = dense A, ragged K (scalar guarded loads; B rows guarded too)
// EPI:   0 = C[r*256+c] = relu(acc + bias[c])
//        2 = C[r*256+c] = acc                      (plain store, no bias/relu)
//        3 = atomicAdd(&C[dst[r]*256+c], relu(acc + bias[c] + Tg[src[r]*256+c]))
//
// Microtile: thread (tx,ty), tx=tid&15, ty=tid>>4
//   rows:  ty*4 + {0..3}  and  64 + ty*4 + {0..3}   (row pairs packed as f32x2)
//   cols:  tx*4 + {0..3}  and  64 + tx*4 + {0..3}
template <int AMODE, int EPI>
__global__ __launch_bounds__(256, 2)
void gemm128(const float* __restrict__ A, int lda, int K,
             const float* __restrict__ Bw,
             const float* __restrict__ bias,
             float* __restrict__ C,
             const int* __restrict__ src,
             const int* __restrict__ dst,
             const float* __restrict__ Tg)
{
    __shared__ float As[2][8][128];
    __shared__ float Bs[2][8][128];
    __shared__ int   s_src[128];
    __shared__ int   s_dst[128];

    const int tid  = threadIdx.x;
    const int row0 = blockIdx.y * 128;
    const int col0 = blockIdx.x * 128;

    const int aRow = tid >> 1;          // 0..127
    const int aCol = (tid & 1) << 2;    // 0 or 4
    const int bRow = tid >> 5;          // 0..7
    const int bCol = (tid & 31) << 2;   // 0..124

    if (EPI == 3) {
        if (tid < 128) {
            s_src[tid] = src[row0 + tid];
            s_dst[tid] = dst[row0 + tid];
        }
        __syncthreads();
    }

    auto load_a = [&](int kt) -> float4 {
        if (AMODE == 0) {
            return *(const float4*)(A + (size_t)(row0 + aRow) * lda + kt + aCol);
        } else {
            float t0 = 0.f, t1 = 0.f, t2 = 0.f, t3 = 0.f;
            const float* arow = A + (size_t)(row0 + aRow) * lda;
            int k0 = kt + aCol;
            if (k0 + 0 < K) t0 = arow[k0 + 0];
            if (k0 + 1 < K) t1 = arow[k0 + 1];
            if (k0 + 2 < K) t2 = arow[k0 + 2];
            if (k0 + 3 < K) t3 = arow[k0 + 3];
            return make_float4(t0, t1, t2, t3);
        }
    };

    auto load_b = [&](int kt) -> float4 {
        int kb = kt + bRow;
        if (AMODE == 1 && kb >= K) return make_float4(0.f, 0.f, 0.f, 0.f);
        return *(const float4*)(Bw + (size_t)kb * 256 + col0 + bCol);
    };

    auto store_tile = [&](int p, float4 a4, float4 b4) {
        As[p][aCol + 0][aRow] = a4.x;
        As[p][aCol + 1][aRow] = a4.y;
        As[p][aCol + 2][aRow] = a4.z;
        As[p][aCol + 3][aRow] = a4.w;
        *(float4*)&Bs[p][bRow][bCol] = b4;
    };

    // acc2[i2][j]: f32x2 pair of rows (2*i2-block) for column j
    unsigned long long acc2[4][8];
#pragma unroll
    for (int i2 = 0; i2 < 4; i2++)
#pragma unroll
        for (int j = 0; j < 8; j++) acc2[i2][j] = 0ULL;

    const int tx = tid & 15;
    const int ty = tid >> 4;

    auto compute = [&](int p) {
#pragma unroll
        for (int kk = 0; kk < 8; kk++) {
            // A fragments: 4 consecutive rows -> 2 natural f32x2 pairs, twice
            ulonglong2 aA = *(const ulonglong2*)&As[p][kk][ty * 4];
            ulonglong2 aB = *(const ulonglong2*)&As[p][kk][64 + ty * 4];
            unsigned long long a2[4];
            a2[0] = aA.x; a2[1] = aA.y; a2[2] = aB.x; a2[3] = aB.y;

            float4 b0 = *(const float4*)&Bs[p][kk][tx * 4];
            float4 b1 = *(const float4*)&Bs[p][kk][64 + tx * 4];
            unsigned long long bb2[8];
            DUP2(bb2[0], b0.x); DUP2(bb2[1], b0.y);
            DUP2(bb2[2], b0.z); DUP2(bb2[3], b0.w);
            DUP2(bb2[4], b1.x); DUP2(bb2[5], b1.y);
            DUP2(bb2[6], b1.z); DUP2(bb2[7], b1.w);
#pragma unroll
            for (int i2 = 0; i2 < 4; i2++)
#pragma unroll
                for (int j = 0; j < 8; j++)
                    FMA2(acc2[i2][j], a2[i2], bb2[j]);
        }
    };

    // prologue: fill buffer 0
    store_tile(0, load_a(0), load_b(0));
    __syncthreads();

    int p = 0;
    for (int kt = 8; kt < K; kt += 8) {
        float4 a4 = load_a(kt);
        float4 b4 = load_b(kt);
        compute(p);
        store_tile(p ^ 1, a4, b4);
        __syncthreads();
        p ^= 1;
    }
    compute(p);

    // unpack accumulators: acc[i][j], i row order {ty*4+0..3, 64+ty*4+0..3}
    float acc[8][8];
#pragma unroll
    for (int i2 = 0; i2 < 4; i2++)
#pragma unroll
        for (int j = 0; j < 8; j++)
            UNPK2(acc[2 * i2][j], acc[2 * i2 + 1][j], acc2[i2][j]);
    // row order after unpack: pairs (0,1),(2,3) are rows ty*4+0..3; pairs (4,5),(6,7) rows 64+ty*4+0..3
    // matches index convention: i<4 -> ty*4+i ; i>=4 -> 64+ty*4+(i-4)

    float bb[8];
    if (EPI != 2) {
#pragma unroll
        for (int j = 0; j < 4; j++) {
            bb[j]     = bias[col0 + tx * 4 + j];
            bb[4 + j] = bias[col0 + 64 + tx * 4 + j];
        }
    }

    if (EPI == 0) {
#pragma unroll
        for (int i = 0; i < 8; i++) {
            int lrow = (i < 4) ? (ty * 4 + i) : (64 + ty * 4 + (i - 4));
            float* cp = C + (size_t)(row0 + lrow) * 256 + col0;
            float4 o0, o1;
            o0.x = fmaxf(acc[i][0] + bb[0], 0.f);
            o0.y = fmaxf(acc[i][1] + bb[1], 0.f);
            o0.z = fmaxf(acc[i][2] + bb[2], 0.f);
            o0.w = fmaxf(acc[i][3] + bb[3], 0.f);
            o1.x = fmaxf(acc[i][4] + bb[4], 0.f);
            o1.y = fmaxf(acc[i][5] + bb[5], 0.f);
            o1.z = fmaxf(acc[i][6] + bb[6], 0.f);
            o1.w = fmaxf(acc[i][7] + bb[7], 0.f);
            *(float4*)(cp + tx * 4)      = o0;
            *(float4*)(cp + 64 + tx * 4) = o1;
        }
    } else if (EPI == 2) {
#pragma unroll
        for (int i = 0; i < 8; i++) {
            int lrow = (i < 4) ? (ty * 4 + i) : (64 + ty * 4 + (i - 4));
            float* cp = C + (size_t)(row0 + lrow) * 256 + col0;
            *(float4*)(cp + tx * 4)      = make_float4(acc[i][0], acc[i][1], acc[i][2], acc[i][3]);
            *(float4*)(cp + 64 + tx * 4) = make_float4(acc[i][4], acc[i][5], acc[i][6], acc[i][7]);
        }
    } else { // EPI == 3
#pragma unroll
        for (int i = 0; i < 8; i++) {
            int lrow = (i < 4) ? (ty * 4 + i) : (64 + ty * 4 + (i - 4));
            int sr = s_src[lrow];
            int d  = s_dst[lrow];
            const float* trow = Tg + (size_t)sr * 256 + col0;
            float4 t0 = *(const float4*)(trow + tx * 4);
            float4 t1 = *(const float4*)(trow + 64 + tx * 4);
            float* base = C + (size_t)d * 256 + col0;
            atomicAdd(base + tx * 4 + 0,      fmaxf(acc[i][0] + bb[0] + t0.x, 0.f));
            atomicAdd(base + tx * 4 + 1,      fmaxf(acc[i][1] + bb[1] + t0.y, 0.f));
            atomicAdd(base + tx * 4 + 2,      fmaxf(acc[i][2] + bb[2] + t0.z, 0.f));
            atomicAdd(base + tx * 4 + 3,      fmaxf(acc[i][3] + bb[3] + t0.w, 0.f));
            atomicAdd(base + 64 + tx * 4 + 0, fmaxf(acc[i][4] + bb[4] + t1.x, 0.f));
            atomicAdd(base + 64 + tx * 4 + 1, fmaxf(acc[i][5] + bb[5] + t1.y, 0.f));
            atomicAdd(base + 64 + tx * 4 + 2, fmaxf(acc[i][6] + bb[6] + t1.z, 0.f));
            atomicAdd(base + 64 + tx * 4 + 3, fmaxf(acc[i][7] + bb[7] + t1.w, 0.f));
        }
    }
}

// ---------------- LayerNorm: h = LN(h + u, g, b), warp per row ----------------
__global__ void ln_kernel(const float* __restrict__ u,
                          const float* __restrict__ lg,
                          const float* __restrict__ lb)
{
    int row  = blockIdx.x * 8 + (threadIdx.x >> 5);
    int lane = threadIdx.x & 31;
    float*       hrow = g_h + (size_t)row * 256;
    const float* urow = u   + (size_t)row * 256;

    float x[8];
    float4 h0 = *(const float4*)(hrow + lane * 4);
    float4 h1 = *(const float4*)(hrow + 128 + lane * 4);
    float4 u0 = *(const float4*)(urow + lane * 4);
    float4 u1 = *(const float4*)(urow + 128 + lane * 4);
    x[0] = h0.x + u0.x; x[1] = h0.y + u0.y; x[2] = h0.z + u0.z; x[3] = h0.w + u0.w;
    x[4] = h1.x + u1.x; x[5] = h1.y + u1.y; x[6] = h1.z + u1.z; x[7] = h1.w + u1.w;

    float s = 0.f, q = 0.f;
#pragma unroll
    for (int j = 0; j < 8; j++) { s += x[j]; q += x[j] * x[j]; }
#pragma unroll
    for (int o = 16; o > 0; o >>= 1) {
        s += __shfl_xor_sync(0xFFFFFFFFu, s, o);
        q += __shfl_xor_sync(0xFFFFFFFFu, q, o);
    }
    float mu  = s * (1.f / 256.f);
    float var = q * (1.f / 256.f) - mu * mu;
    float rs  = rsqrtf(var + 1e-5f);

    float4 g0 = *(const float4*)(lg + lane * 4);
    float4 g1 = *(const float4*)(lg + 128 + lane * 4);
    float4 b0 = *(const float4*)(lb + lane * 4);
    float4 b1 = *(const float4*)(lb + 128 + lane * 4);

    float4 y0, y1;
    y0.x = (x[0] - mu) * rs * g0.x + b0.x;
    y0.y = (x[1] - mu) * rs * g0.y + b0.y;
    y0.z = (x[2] - mu) * rs * g0.z + b0.z;
    y0.w = (x[3] - mu) * rs * g0.w + b0.w;
    y1.x = (x[4] - mu) * rs * g1.x + b1.x;
    y1.y = (x[5] - mu) * rs * g1.y + b1.y;
    y1.z = (x[6] - mu) * rs * g1.z + b1.z;
    y1.w = (x[7] - mu) * rs * g1.w + b1.w;
    *(float4*)(hrow + lane * 4)       = y0;
    *(float4*)(hrow + 128 + lane * 4) = y1;
}

// ---------------- segment starts from sorted b ----------------
__global__ void seg_starts(const int* __restrict__ b)
{
    int i = blockIdx.x * blockDim.x + threadIdx.x;
    if (i >= NN) return;
    int cur = b[i];
    if (i == 0) {
        for (int g = 0; g <= cur; g++) g_starts[g] = 0;
    } else {
        int prev = b[i - 1];
        if (prev != cur)
            for (int g = prev + 1; g <= cur; g++) g_starts[g] = i;
    }
    if (i == NN - 1)
        for (int g = cur + 1; g <= BBG; g++) g_starts[g] = NN;
}

// ---------------- readout: mean || max per graph ----------------
__global__ void readout_kernel(void)
{
    int g = blockIdx.x;
    int s = g_starts[g], en = g_starts[g + 1];
    int c = threadIdx.x;
    float sum = 0.f, mx = -INFINITY;
    for (int r = s; r < en; r++) {
        float v = g_h[(size_t)r * 256 + c];
        sum += v;
        mx = fmaxf(mx, v);
    }
    int   cnt   = en - s;
    float denom = (cnt > 0) ? (float)cnt : 1.f;
    g_gout[(size_t)g * 512 + c]       = sum / denom;
    g_gout[(size_t)g * 512 + 256 + c] = (cnt > 0) ? mx : 0.f;
}

// ---------------- FiLM + predictor, 8 graphs per block ----------------
__global__ __launch_bounds__(256)
void film_pred(const float* __restrict__ ctx, const int* __restrict__ pid,
               const float* __restrict__ gW1, const float* __restrict__ gb1,
               const float* __restrict__ glng, const float* __restrict__ glnb,
               const float* __restrict__ gW2, const float* __restrict__ gb2,
               const float* __restrict__ bW1, const float* __restrict__ bb1,
               const float* __restrict__ blng, const float* __restrict__ blnb,
               const float* __restrict__ bW2, const float* __restrict__ bb2,
               const float* __restrict__ pW1, const float* __restrict__ pb1,
               const float* __restrict__ pW2, const float* __restrict__ pb2,
               float* __restrict__ out)
{
    __shared__ float s_c[8][128];
    __shared__ float s_t[8][256];
    __shared__ float s_hmod[8][512];

    int tid = threadIdx.x;
    int g0  = blockIdx.x * 8;

    for (int i = tid; i < 8 * 128; i += 256) {
        int r = i >> 7, k = i & 127;
        s_c[r][k] = ctx[(size_t)pid[g0 + r] * 128 + k];
    }
    __syncthreads();

#pragma unroll
    for (int net = 0; net < 2; net++) {
        const float* W1 = net ? bW1 : gW1;
        const float* B1 = net ? bb1 : gb1;
        const float* LG = net ? blng : glng;
        const float* LB = net ? blnb : glnb;
        const float* W2 = net ? bW2 : gW2;
        const float* B2 = net ? bb2 : gb2;

        float a1[8];
#pragma unroll
        for (int r = 0; r < 8; r++) a1[r] = B1[tid];
        for (int k = 0; k < 128; k++) {
            float w = W1[k * 256 + tid];
#pragma unroll
            for (int r = 0; r < 8; r++) a1[r] += s_c[r][k] * w;
        }
#pragma unroll
        for (int r = 0; r < 8; r++) s_t[r][tid] = a1[r];
        __syncthreads();

        {
            int r = tid >> 5, lane = tid & 31;
            float x[8], s = 0.f, q = 0.f;
#pragma unroll
            for (int j = 0; j < 8; j++) {
                x[j] = s_t[r][lane + 32 * j];
                s += x[j]; q += x[j] * x[j];
            }
#pragma unroll
            for (int o = 16; o > 0; o >>= 1) {
                s += __shfl_xor_sync(0xFFFFFFFFu, s, o);
                q += __shfl_xor_sync(0xFFFFFFFFu, q, o);
            }
            float mu  = s * (1.f / 256.f);
            float var = q * (1.f / 256.f) - mu * mu;
            float rs  = rsqrtf(var + 1e-5f);
#pragma unroll
            for (int j = 0; j < 8; j++) {
                int c = lane + 32 * j;
                float y = (x[j] - mu) * rs * LG[c] + LB[c];
                s_t[r][c] = fmaxf(y, 0.f);
            }
        }
        __syncthreads();

        float a20[8], a21[8];
#pragma unroll
        for (int r = 0; r < 8; r++) { a20[r] = 0.f; a21[r] = 0.f; }
        for (int k = 0; k < 256; k++) {
            float w0 = W2[k * 512 + tid];
            float w1 = W2[k * 512 + tid + 256];
#pragma unroll
            for (int r = 0; r < 8; r++) {
                float t = s_t[r][k];
                a20[r] += t * w0;
                a21[r] += t * w1;
            }
        }
        float bc0 = B2[tid], bc1 = B2[tid + 256];
        if (net == 0) {
#pragma unroll
            for (int r = 0; r < 8; r++) {
                s_hmod[r][tid]       = (a20[r] + bc0) * g_gout[(size_t)(g0 + r) * 512 + tid];
                s_hmod[r][tid + 256] = (a21[r] + bc1) * g_gout[(size_t)(g0 + r) * 512 + tid + 256];
            }
        } else {
#pragma unroll
            for (int r = 0; r < 8; r++) {
                s_hmod[r][tid]       += a20[r] + bc0;
                s_hmod[r][tid + 256] += a21[r] + bc1;
            }
        }
        __syncthreads();
    }

    float az[8];
#pragma unroll
    for (int r = 0; r < 8; r++) az[r] = pb1[tid];
    for (int k = 0; k < 512; k++) {
        float w = pW1[k * 256 + tid];
#pragma unroll
        for (int r = 0; r < 8; r++) az[r] += s_hmod[r][k] * w;
    }
#pragma unroll
    for (int r = 0; r < 8; r++) s_t[r][tid] = fmaxf(az[r], 0.f);
    __syncthreads();

    {
        int r = tid >> 5, lane = tid & 31;
        float p = 0.f;
#pragma unroll
        for (int j = 0; j < 8; j++) {
            int c = lane + 32 * j;
            p += s_t[r][c] * pW2[c];
        }
#pragma unroll
        for (int o = 16; o > 0; o >>= 1) p += __shfl_xor_sync(0xFFFFFFFFu, p, o);
        if (lane == 0) out[g0 + r] = p + pb2[0];
    }
}

// ---------------- host launcher ----------------
extern "C" void kernel_launch(void* const* d_in, const int* in_sizes, int n_in,
                              void* d_out, int out_size)
{
    (void)in_sizes; (void)n_in; (void)out_size;

    const float* nf   = (const float*)d_in[0];
    const int*   ei   = (const int*)  d_in[1];
    const float* ef   = (const float*)d_in[2];
    const int*   bseg = (const int*)  d_in[3];
    const int*   pid  = (const int*)  d_in[4];
    const float* Wn   = (const float*)d_in[5];
    const float* bn   = (const float*)d_in[6];
    const float* We   = (const float*)d_in[7];
    const float* be   = (const float*)d_in[8];
    const float* Wm   = (const float*)d_in[9];
    const float* bm   = (const float*)d_in[10];
    const float* Wu   = (const float*)d_in[11];
    const float* bu   = (const float*)d_in[12];
    const float* lng  = (const float*)d_in[13];
    const float* lnb  = (const float*)d_in[14];
    const float* ctx  = (const float*)d_in[15];
    const float* gW1  = (const float*)d_in[16];
    const float* gb1  = (const float*)d_in[17];
    const float* glng = (const float*)d_in[18];
    const float* glnb = (const float*)d_in[19];
    const float* gW2  = (const float*)d_in[20];
    const float* gb2  = (const float*)d_in[21];
    const float* bW1  = (const float*)d_in[22];
    const float* bb1  = (const float*)d_in[23];
    const float* blng = (const float*)d_in[24];
    const float* blnb = (const float*)d_in[25];
    const float* bW2  = (const float*)d_in[26];
    const float* bb2  = (const float*)d_in[27];
    const float* pW1  = (const float*)d_in[28];
    const float* pb1  = (const float*)d_in[29];
    const float* pW2  = (const float*)d_in[30];
    const float* pb2  = (const float*)d_in[31];
    float* out = (float*)d_out;

    const int* src = ei;
    const int* dst = ei + EE;

    float *h_ptr, *e_ptr, *agg_ptr, *u_ptr, *t_ptr;
    cudaGetSymbolAddress((void**)&h_ptr,   g_h);
    cudaGetSymbolAddress((void**)&e_ptr,   g_e);
    cudaGetSymbolAddress((void**)&agg_ptr, g_agg);
    cudaGetSymbolAddress((void**)&u_ptr,   g_u);
    cudaGetSymbolAddress((void**)&t_ptr,   g_t);

    dim3 thr(256);

    // input embeddings
    gemm128<1, 0><<<dim3(2, NN / 128), thr>>>(nf, 69, 69, Wn, bn, h_ptr, nullptr, nullptr, nullptr);
    gemm128<1, 0><<<dim3(2, EE / 128), thr>>>(ef, 9, 9, We, be, e_ptr, nullptr, nullptr, nullptr);

    // MPNN layers
    for (int l = 0; l < LLAY; l++) {
        const float* WmTop = Wm + (size_t)l * 512 * 256;          // rows 0..255   (h part)
        const float* WmBot = WmTop + (size_t)256 * 256;           // rows 256..511 (e part)

        cudaMemsetAsync(agg_ptr, 0, (size_t)NN * HIDD * sizeof(float), 0);

        // t = h @ Wm_top   (no bias, no relu)
        gemm128<0, 2><<<dim3(2, NN / 128), thr>>>(
            h_ptr, 256, 256, WmTop, nullptr, t_ptr, nullptr, nullptr, nullptr);

        // agg[dst] += relu(e @ Wm_bot + bm + t[src])
        gemm128<0, 3><<<dim3(2, EE / 128), thr>>>(
            e_ptr, 256, 256, WmBot, bm + (size_t)l * 256, agg_ptr, src, dst, t_ptr);

        // u = relu(agg @ Wu + bu)
        gemm128<0, 0><<<dim3(2, NN / 128), thr>>>(
            agg_ptr, 256, 256, Wu + (size_t)l * 256 * 256, bu + (size_t)l * 256,
            u_ptr, nullptr, nullptr, nullptr);

        // h = LN(h + u)
        ln_kernel<<<NN / 8, 256>>>(u_ptr, lng + (size_t)l * 256, lnb + (size_t)l * 256);
    }

    // readout + FiLM + predictor
    seg_starts<<<NN / 256, 256>>>(bseg);
    readout_kernel<<<BBG, 256>>>();
    film_pred<<<BBG / 8, 256>>>(ctx, pid,
                                gW1, gb1, glng, glnb, gW2, gb2,
                                bW1, bb1, blng, blnb, bW2, bb2,
                                pW1, pb1, pW2, pb2, out);
}

// round 7
// speedup vs baseline: 1.6472x; 1.0027x over previous
#include <cuda_runtime.h>
#include <math.h>

#define NN   131072
#define EE   262144
#define BBG  4096
#define HIDD 256
#define LLAY 4

// ---------------- scratch (device globals; no allocation) ----------------
__device__ float g_h[(size_t)NN * HIDD];     // node states
__device__ float g_e[(size_t)EE * HIDD];     // edge embeddings
__device__ float g_agg[(size_t)NN * HIDD];   // scatter-add target
__device__ float g_u[(size_t)NN * HIDD];     // update GEMM out
__device__ float g_t[(size_t)NN * HIDD];     // per-node message part (h @ Wm_top)
__device__ float g_gout[(size_t)BBG * 512];  // readout [B,512]
__device__ int   g_starts[BBG + 1];

// packed dual-fp32 helpers (sm_103a)
#define DUP2(d, f)   asm("mov.b64 %0, {%1, %1};" : "=l"(d) : "f"(f))
#define FMA2(c, a, b) asm("fma.rn.f32x2 %0, %1, %2, %0;" : "+l"(c) : "l"(a), "l"(b))
#define UNPK2(lo, hi, v) asm("mov.b64 {%0, %1}, %2;" : "=f"(lo), "=f"(hi) : "l"(v))

// ---------------- generic 128x128x8 tiled SGEMM (double-buffered, f32x2) ----------------
// AMODE: 0 = dense A, K%8==0, rows 16B-aligned (vec4 loads)
//        1 = dense A, ragged K (scalar guarded loads; B rows guarded too)
// EPI:   0 = C[r*256+c] = relu(acc + bias[c])
//        2 = C[r*256+c] = acc                      (plain store, no bias/relu)
//        3 = vector-RED: agg[dst[r]] += relu(acc + bias + Tg[src[r]])  (float4 atomics)
template <int AMODE, int EPI>
__global__ __launch_bounds__(256, 2)
void gemm128(const float* __restrict__ A, int lda, int K,
             const float* __restrict__ Bw,
             const float* __restrict__ bias,
             float* __restrict__ C,
             const int* __restrict__ src,
             const int* __restrict__ dst,
             const float* __restrict__ Tg)
{
    __shared__ float As[2][8][128];
    __shared__ float Bs[2][8][128];
    __shared__ int   s_src[128];
    __shared__ int   s_dst[128];

    const int tid  = threadIdx.x;
    const int row0 = blockIdx.y * 128;
    const int col0 = blockIdx.x * 128;

    const int aRow = tid >> 1;          // 0..127
    const int aCol = (tid & 1) << 2;    // 0 or 4
    const int bRow = tid >> 5;          // 0..7
    const int bCol = (tid & 31) << 2;   // 0..124

    if (EPI == 3) {
        if (tid < 128) {
            s_src[tid] = src[row0 + tid];
            s_dst[tid] = dst[row0 + tid];
        }
        __syncthreads();
    }

    auto load_a = [&](int kt) -> float4 {
        if (AMODE == 0) {
            return *(const float4*)(A + (size_t)(row0 + aRow) * lda + kt + aCol);
        } else {
            float t0 = 0.f, t1 = 0.f, t2 = 0.f, t3 = 0.f;
            const float* arow = A + (size_t)(row0 + aRow) * lda;
            int k0 = kt + aCol;
            if (k0 + 0 < K) t0 = arow[k0 + 0];
            if (k0 + 1 < K) t1 = arow[k0 + 1];
            if (k0 + 2 < K) t2 = arow[k0 + 2];
            if (k0 + 3 < K) t3 = arow[k0 + 3];
            return make_float4(t0, t1, t2, t3);
        }
    };

    auto load_b = [&](int kt) -> float4 {
        int kb = kt + bRow;
        if (AMODE == 1 && kb >= K) return make_float4(0.f, 0.f, 0.f, 0.f);
        return *(const float4*)(Bw + (size_t)kb * 256 + col0 + bCol);
    };

    auto store_tile = [&](int p, float4 a4, float4 b4) {
        As[p][aCol + 0][aRow] = a4.x;
        As[p][aCol + 1][aRow] = a4.y;
        As[p][aCol + 2][aRow] = a4.z;
        As[p][aCol + 3][aRow] = a4.w;
        *(float4*)&Bs[p][bRow][bCol] = b4;
    };

    // acc2[i2][j]: f32x2 pair of rows for column j
    unsigned long long acc2[4][8];
#pragma unroll
    for (int i2 = 0; i2 < 4; i2++)
#pragma unroll
        for (int j = 0; j < 8; j++) acc2[i2][j] = 0ULL;

    const int tx = tid & 15;
    const int ty = tid >> 4;

    auto compute = [&](int p) {
#pragma unroll
        for (int kk = 0; kk < 8; kk++) {
            ulonglong2 aA = *(const ulonglong2*)&As[p][kk][ty * 4];
            ulonglong2 aB = *(const ulonglong2*)&As[p][kk][64 + ty * 4];
            unsigned long long a2[4];
            a2[0] = aA.x; a2[1] = aA.y; a2[2] = aB.x; a2[3] = aB.y;

            float4 b0 = *(const float4*)&Bs[p][kk][tx * 4];
            float4 b1 = *(const float4*)&Bs[p][kk][64 + tx * 4];
            unsigned long long bb2[8];
            DUP2(bb2[0], b0.x); DUP2(bb2[1], b0.y);
            DUP2(bb2[2], b0.z); DUP2(bb2[3], b0.w);
            DUP2(bb2[4], b1.x); DUP2(bb2[5], b1.y);
            DUP2(bb2[6], b1.z); DUP2(bb2[7], b1.w);
#pragma unroll
            for (int i2 = 0; i2 < 4; i2++)
#pragma unroll
                for (int j = 0; j < 8; j++)
                    FMA2(acc2[i2][j], a2[i2], bb2[j]);
        }
    };

    // prologue: fill buffer 0
    store_tile(0, load_a(0), load_b(0));
    __syncthreads();

    int p = 0;
    for (int kt = 8; kt < K; kt += 8) {
        float4 a4 = load_a(kt);
        float4 b4 = load_b(kt);
        compute(p);
        store_tile(p ^ 1, a4, b4);
        __syncthreads();
        p ^= 1;
    }
    compute(p);

    // unpack accumulators: i<4 -> row ty*4+i ; i>=4 -> row 64+ty*4+(i-4)
    float acc[8][8];
#pragma unroll
    for (int i2 = 0; i2 < 4; i2++)
#pragma unroll
        for (int j = 0; j < 8; j++)
            UNPK2(acc[2 * i2][j], acc[2 * i2 + 1][j], acc2[i2][j]);

    float bb[8];
    if (EPI != 2) {
#pragma unroll
        for (int j = 0; j < 4; j++) {
            bb[j]     = bias[col0 + tx * 4 + j];
            bb[4 + j] = bias[col0 + 64 + tx * 4 + j];
        }
    }

    if (EPI == 0) {
#pragma unroll
        for (int i = 0; i < 8; i++) {
            int lrow = (i < 4) ? (ty * 4 + i) : (64 + ty * 4 + (i - 4));
            float* cp = C + (size_t)(row0 + lrow) * 256 + col0;
            float4 o0, o1;
            o0.x = fmaxf(acc[i][0] + bb[0], 0.f);
            o0.y = fmaxf(acc[i][1] + bb[1], 0.f);
            o0.z = fmaxf(acc[i][2] + bb[2], 0.f);
            o0.w = fmaxf(acc[i][3] + bb[3], 0.f);
            o1.x = fmaxf(acc[i][4] + bb[4], 0.f);
            o1.y = fmaxf(acc[i][5] + bb[5], 0.f);
            o1.z = fmaxf(acc[i][6] + bb[6], 0.f);
            o1.w = fmaxf(acc[i][7] + bb[7], 0.f);
            *(float4*)(cp + tx * 4)      = o0;
            *(float4*)(cp + 64 + tx * 4) = o1;
        }
    } else if (EPI == 2) {
#pragma unroll
        for (int i = 0; i < 8; i++) {
            int lrow = (i < 4) ? (ty * 4 + i) : (64 + ty * 4 + (i - 4));
            float* cp = C + (size_t)(row0 + lrow) * 256 + col0;
            *(float4*)(cp + tx * 4)      = make_float4(acc[i][0], acc[i][1], acc[i][2], acc[i][3]);
            *(float4*)(cp + 64 + tx * 4) = make_float4(acc[i][4], acc[i][5], acc[i][6], acc[i][7]);
        }
    } else { // EPI == 3: vectorized 16B reductions (REDG), 16 per thread instead of 64
#pragma unroll
        for (int i = 0; i < 8; i++) {
            int lrow = (i < 4) ? (ty * 4 + i) : (64 + ty * 4 + (i - 4));
            int sr = s_src[lrow];
            int d  = s_dst[lrow];
            const float* trow = Tg + (size_t)sr * 256 + col0;
            float4 t0 = *(const float4*)(trow + tx * 4);
            float4 t1 = *(const float4*)(trow + 64 + tx * 4);
            float* base = C + (size_t)d * 256 + col0;
            float4 v0, v1;
            v0.x = fmaxf(acc[i][0] + bb[0] + t0.x, 0.f);
            v0.y = fmaxf(acc[i][1] + bb[1] + t0.y, 0.f);
            v0.z = fmaxf(acc[i][2] + bb[2] + t0.z, 0.f);
            v0.w = fmaxf(acc[i][3] + bb[3] + t0.w, 0.f);
            v1.x = fmaxf(acc[i][4] + bb[4] + t1.x, 0.f);
            v1.y = fmaxf(acc[i][5] + bb[5] + t1.y, 0.f);
            v1.z = fmaxf(acc[i][6] + bb[6] + t1.z, 0.f);
            v1.w = fmaxf(acc[i][7] + bb[7] + t1.w, 0.f);
            atomicAdd((float4*)(base + tx * 4),      v0);   // sm_90+: 16B vector RED
            atomicAdd((float4*)(base + 64 + tx * 4), v1);
        }
    }
}

// ---------------- LayerNorm: h = LN(h + u, g, b), warp per row ----------------
__global__ void ln_kernel(const float* __restrict__ u,
                          const float* __restrict__ lg,
                          const float* __restrict__ lb)
{
    int row  = blockIdx.x * 8 + (threadIdx.x >> 5);
    int lane = threadIdx.x & 31;
    float*       hrow = g_h + (size_t)row * 256;
    const float* urow = u   + (size_t)row * 256;

    float x[8];
    float4 h0 = *(const float4*)(hrow + lane * 4);
    float4 h1 = *(const float4*)(hrow + 128 + lane * 4);
    float4 u0 = *(const float4*)(urow + lane * 4);
    float4 u1 = *(const float4*)(urow + 128 + lane * 4);
    x[0] = h0.x + u0.x; x[1] = h0.y + u0.y; x[2] = h0.z + u0.z; x[3] = h0.w + u0.w;
    x[4] = h1.x + u1.x; x[5] = h1.y + u1.y; x[6] = h1.z + u1.z; x[7] = h1.w + u1.w;

    float s = 0.f, q = 0.f;
#pragma unroll
    for (int j = 0; j < 8; j++) { s += x[j]; q += x[j] * x[j]; }
#pragma unroll
    for (int o = 16; o > 0; o >>= 1) {
        s += __shfl_xor_sync(0xFFFFFFFFu, s, o);
        q += __shfl_xor_sync(0xFFFFFFFFu, q, o);
    }
    float mu  = s * (1.f / 256.f);
    float var = q * (1.f / 256.f) - mu * mu;
    float rs  = rsqrtf(var + 1e-5f);

    float4 g0 = *(const float4*)(lg + lane * 4);
    float4 g1 = *(const float4*)(lg + 128 + lane * 4);
    float4 b0 = *(const float4*)(lb + lane * 4);
    float4 b1 = *(const float4*)(lb + 128 + lane * 4);

    float4 y0, y1;
    y0.x = (x[0] - mu) * rs * g0.x + b0.x;
    y0.y = (x[1] - mu) * rs * g0.y + b0.y;
    y0.z = (x[2] - mu) * rs * g0.z + b0.z;
    y0.w = (x[3] - mu) * rs * g0.w + b0.w;
    y1.x = (x[4] - mu) * rs * g1.x + b1.x;
    y1.y = (x[5] - mu) * rs * g1.y + b1.y;
    y1.z = (x[6] - mu) * rs * g1.z + b1.z;
    y1.w = (x[7] - mu) * rs * g1.w + b1.w;
    *(float4*)(hrow + lane * 4)       = y0;
    *(float4*)(hrow + 128 + lane * 4) = y1;
}

// ---------------- segment starts from sorted b ----------------
__global__ void seg_starts(const int* __restrict__ b)
{
    int i = blockIdx.x * blockDim.x + threadIdx.x;
    if (i >= NN) return;
    int cur = b[i];
    if (i == 0) {
        for (int g = 0; g <= cur; g++) g_starts[g] = 0;
    } else {
        int prev = b[i - 1];
        if (prev != cur)
            for (int g = prev + 1; g <= cur; g++) g_starts[g] = i;
    }
    if (i == NN - 1)
        for (int g = cur + 1; g <= BBG; g++) g_starts[g] = NN;
}

// ---------------- readout: mean || max per graph ----------------
__global__ void readout_kernel(void)
{
    int g = blockIdx.x;
    int s = g_starts[g], en = g_starts[g + 1];
    int c = threadIdx.x;
    float sum = 0.f, mx = -INFINITY;
    for (int r = s; r < en; r++) {
        float v = g_h[(size_t)r * 256 + c];
        sum += v;
        mx = fmaxf(mx, v);
    }
    int   cnt   = en - s;
    float denom = (cnt > 0) ? (float)cnt : 1.f;
    g_gout[(size_t)g * 512 + c]       = sum / denom;
    g_gout[(size_t)g * 512 + 256 + c] = (cnt > 0) ? mx : 0.f;
}

// ---------------- FiLM + predictor, 8 graphs per block ----------------
__global__ __launch_bounds__(256)
void film_pred(const float* __restrict__ ctx, const int* __restrict__ pid,
               const float* __restrict__ gW1, const float* __restrict__ gb1,
               const float* __restrict__ glng, const float* __restrict__ glnb,
               const float* __restrict__ gW2, const float* __restrict__ gb2,
               const float* __restrict__ bW1, const float* __restrict__ bb1,
               const float* __restrict__ blng, const float* __restrict__ blnb,
               const float* __restrict__ bW2, const float* __restrict__ bb2,
               const float* __restrict__ pW1, const float* __restrict__ pb1,
               const float* __restrict__ pW2, const float* __restrict__ pb2,
               float* __restrict__ out)
{
    __shared__ float s_c[8][128];
    __shared__ float s_t[8][256];
    __shared__ float s_hmod[8][512];

    int tid = threadIdx.x;
    int g0  = blockIdx.x * 8;

    for (int i = tid; i < 8 * 128; i += 256) {
        int r = i >> 7, k = i & 127;
        s_c[r][k] = ctx[(size_t)pid[g0 + r] * 128 + k];
    }
    __syncthreads();

#pragma unroll
    for (int net = 0; net < 2; net++) {
        const float* W1 = net ? bW1 : gW1;
        const float* B1 = net ? bb1 : gb1;
        const float* LG = net ? blng : glng;
        const float* LB = net ? blnb : glnb;
        const float* W2 = net ? bW2 : gW2;
        const float* B2 = net ? bb2 : gb2;

        float a1[8];
#pragma unroll
        for (int r = 0; r < 8; r++) a1[r] = B1[tid];
        for (int k = 0; k < 128; k++) {
            float w = W1[k * 256 + tid];
#pragma unroll
            for (int r = 0; r < 8; r++) a1[r] += s_c[r][k] * w;
        }
#pragma unroll
        for (int r = 0; r < 8; r++) s_t[r][tid] = a1[r];
        __syncthreads();

        {
            int r = tid >> 5, lane = tid & 31;
            float x[8], s = 0.f, q = 0.f;
#pragma unroll
            for (int j = 0; j < 8; j++) {
                x[j] = s_t[r][lane + 32 * j];
                s += x[j]; q += x[j] * x[j];
            }
#pragma unroll
            for (int o = 16; o > 0; o >>= 1) {
                s += __shfl_xor_sync(0xFFFFFFFFu, s, o);
                q += __shfl_xor_sync(0xFFFFFFFFu, q, o);
            }
            float mu  = s * (1.f / 256.f);
            float var = q * (1.f / 256.f) - mu * mu;
            float rs  = rsqrtf(var + 1e-5f);
#pragma unroll
            for (int j = 0; j < 8; j++) {
                int c = lane + 32 * j;
                float y = (x[j] - mu) * rs * LG[c] + LB[c];
                s_t[r][c] = fmaxf(y, 0.f);
            }
        }
        __syncthreads();

        float a20[8], a21[8];
#pragma unroll
        for (int r = 0; r < 8; r++) { a20[r] = 0.f; a21[r] = 0.f; }
        for (int k = 0; k < 256; k++) {
            float w0 = W2[k * 512 + tid];
            float w1 = W2[k * 512 + tid + 256];
#pragma unroll
            for (int r = 0; r < 8; r++) {
                float t = s_t[r][k];
                a20[r] += t * w0;
                a21[r] += t * w1;
            }
        }
        float bc0 = B2[tid], bc1 = B2[tid + 256];
        if (net == 0) {
#pragma unroll
            for (int r = 0; r < 8; r++) {
                s_hmod[r][tid]       = (a20[r] + bc0) * g_gout[(size_t)(g0 + r) * 512 + tid];
                s_hmod[r][tid + 256] = (a21[r] + bc1) * g_gout[(size_t)(g0 + r) * 512 + tid + 256];
            }
        } else {
#pragma unroll
            for (int r = 0; r < 8; r++) {
                s_hmod[r][tid]       += a20[r] + bc0;
                s_hmod[r][tid + 256] += a21[r] + bc1;
            }
        }
        __syncthreads();
    }

    float az[8];
#pragma unroll
    for (int r = 0; r < 8; r++) az[r] = pb1[tid];
    for (int k = 0; k < 512; k++) {
        float w = pW1[k * 256 + tid];
#pragma unroll
        for (int r = 0; r < 8; r++) az[r] += s_hmod[r][k] * w;
    }
#pragma unroll
    for (int r = 0; r < 8; r++) s_t[r][tid] = fmaxf(az[r], 0.f);
    __syncthreads();

    {
        int r = tid >> 5, lane = tid & 31;
        float p = 0.f;
#pragma unroll
        for (int j = 0; j < 8; j++) {
            int c = lane + 32 * j;
            p += s_t[r][c] * pW2[c];
        }
#pragma unroll
        for (int o = 16; o > 0; o >>= 1) p += __shfl_xor_sync(0xFFFFFFFFu, p, o);
        if (lane == 0) out[g0 + r] = p + pb2[0];
    }
}

// ---------------- host launcher ----------------
extern "C" void kernel_launch(void* const* d_in, const int* in_sizes, int n_in,
                              void* d_out, int out_size)
{
    (void)in_sizes; (void)n_in; (void)out_size;

    const float* nf   = (const float*)d_in[0];
    const int*   ei   = (const int*)  d_in[1];
    const float* ef   = (const float*)d_in[2];
    const int*   bseg = (const int*)  d_in[3];
    const int*   pid  = (const int*)  d_in[4];
    const float* Wn   = (const float*)d_in[5];
    const float* bn   = (const float*)d_in[6];
    const float* We   = (const float*)d_in[7];
    const float* be   = (const float*)d_in[8];
    const float* Wm   = (const float*)d_in[9];
    const float* bm   = (const float*)d_in[10];
    const float* Wu   = (const float*)d_in[11];
    const float* bu   = (const float*)d_in[12];
    const float* lng  = (const float*)d_in[13];
    const float* lnb  = (const float*)d_in[14];
    const float* ctx  = (const float*)d_in[15];
    const float* gW1  = (const float*)d_in[16];
    const float* gb1  = (const float*)d_in[17];
    const float* glng = (const float*)d_in[18];
    const float* glnb = (const float*)d_in[19];
    const float* gW2  = (const float*)d_in[20];
    const float* gb2  = (const float*)d_in[21];
    const float* bW1  = (const float*)d_in[22];
    const float* bb1  = (const float*)d_in[23];
    const float* blng = (const float*)d_in[24];
    const float* blnb = (const float*)d_in[25];
    const float* bW2  = (const float*)d_in[26];
    const float* bb2  = (const float*)d_in[27];
    const float* pW1  = (const float*)d_in[28];
    const float* pb1  = (const float*)d_in[29];
    const float* pW2  = (const float*)d_in[30];
    const float* pb2  = (const float*)d_in[31];
    float* out = (float*)d_out;

    const int* src = ei;
    const int* dst = ei + EE;

    float *h_ptr, *e_ptr, *agg_ptr, *u_ptr, *t_ptr;
    cudaGetSymbolAddress((void**)&h_ptr,   g_h);
    cudaGetSymbolAddress((void**)&e_ptr,   g_e);
    cudaGetSymbolAddress((void**)&agg_ptr, g_agg);
    cudaGetSymbolAddress((void**)&u_ptr,   g_u);
    cudaGetSymbolAddress((void**)&t_ptr,   g_t);

    dim3 thr(256);

    // input embeddings
    gemm128<1, 0><<<dim3(2, NN / 128), thr>>>(nf, 69, 69, Wn, bn, h_ptr, nullptr, nullptr, nullptr);
    gemm128<1, 0><<<dim3(2, EE / 128), thr>>>(ef, 9, 9, We, be, e_ptr, nullptr, nullptr, nullptr);

    // MPNN layers
    for (int l = 0; l < LLAY; l++) {
        const float* WmTop = Wm + (size_t)l * 512 * 256;          // rows 0..255   (h part)
        const float* WmBot = WmTop + (size_t)256 * 256;           // rows 256..511 (e part)

        cudaMemsetAsync(agg_ptr, 0, (size_t)NN * HIDD * sizeof(float), 0);

        // t = h @ Wm_top   (no bias, no relu)
        gemm128<0, 2><<<dim3(2, NN / 128), thr>>>(
            h_ptr, 256, 256, WmTop, nullptr, t_ptr, nullptr, nullptr, nullptr);

        // agg[dst] += relu(e @ Wm_bot + bm + t[src])   (vector REDs)
        gemm128<0, 3><<<dim3(2, EE / 128), thr>>>(
            e_ptr, 256, 256, WmBot, bm + (size_t)l * 256, agg_ptr, src, dst, t_ptr);

        // u = relu(agg @ Wu + bu)
        gemm128<0, 0><<<dim3(2, NN / 128), thr>>>(
            agg_ptr, 256, 256, Wu + (size_t)l * 256 * 256, bu + (size_t)l * 256,
            u_ptr, nullptr, nullptr, nullptr);

        // h = LN(h + u)
        ln_kernel<<<NN / 8, 256>>>(u_ptr, lng + (size_t)l * 256, lnb + (size_t)l * 256);
    }

    // readout + FiLM + predictor
    seg_starts<<<NN / 256, 256>>>(bseg);
    readout_kernel<<<BBG, 256>>>();
    film_pred<<<BBG / 8, 256>>>(ctx, pid,
                                gW1, gb1, glng, glnb, gW2, gb2,
                                bW1, bb1, blng, blnb, bW2, bb2,
                                pW1, pb1, pW2, pb2, out);
}

// round 9
// speedup vs baseline: 2.1460x; 1.3029x over previous
#include <cuda_runtime.h>
#include <cuda_bf16.h>
#include <math.h>
#include <stdint.h>

#define NN   131072
#define EE   262144
#define BBG  4096
#define HIDD 256
#define LLAY 4

// ---------------- scratch (device globals; no allocation) ----------------
__device__ float g_h[(size_t)NN * HIDD];
__device__ float g_e[(size_t)EE * HIDD];
__device__ float g_agg[(size_t)NN * HIDD];
__device__ float g_u[(size_t)NN * HIDD];
__device__ float g_t[(size_t)NN * HIDD];
__device__ float g_gout[(size_t)BBG * 512];
__device__ int   g_starts[BBG + 1];
// transposed + bf16-split weights: 12 matrices of [256(n)][256(k)] bf16
// m=0..3: Wm_top layer m ; m=4..7: Wm_bot layer m-4 ; m=8..11: Wu layer m-8
__device__ __nv_bfloat16 g_wThi[12 * 256 * 256];
__device__ __nv_bfloat16 g_wTlo[12 * 256 * 256];

// ---------------- PTX helpers ----------------
__device__ __forceinline__ uint32_t smem_u32(const void* p) {
    uint32_t a;
    asm("{ .reg .u64 t; cvta.to.shared.u64 t, %1; cvt.u32.u64 %0, t; }" : "=r"(a) : "l"(p));
    return a;
}
#define LDSM4(r0, r1, r2, r3, addr) \
    asm volatile("ldmatrix.sync.aligned.m8n8.x4.shared.b16 {%0,%1,%2,%3}, [%4];" \
        : "=r"(r0), "=r"(r1), "=r"(r2), "=r"(r3) : "r"(addr))
#define MMA_BF16(c, a0, a1, a2, a3, b0, b1) \
    asm volatile("mma.sync.aligned.m16n8k16.row.col.f32.bf16.bf16.f32 " \
        "{%0,%1,%2,%3}, {%4,%5,%6,%7}, {%8,%9}, {%0,%1,%2,%3};" \
        : "+f"((c)[0]), "+f"((c)[1]), "+f"((c)[2]), "+f"((c)[3]) \
        : "r"(a0), "r"(a1), "r"(a2), "r"(a3), "r"(b0), "r"(b1))

// ---------------- mma.sync bf16x3 GEMM: C[M,256] = A[M,256] @ WT^T ----------------
// 128x128 C tile per CTA, 256 threads = 8 warps in 4(m) x 2(n); warp tile 32x64.
// smem mainloop: Ahi/Alo/Bhi/Blo tiles 128 rows x 32 bf16, row stride 80B (conflict-free).
// smem epilogue: C staged as float[128][132].
// EPI 0: C = relu(acc+bias)   EPI 2: C = acc   EPI 3: agg[dst] +=RED relu(acc+bias+Tg[src])
#define OFF_AHI 0
#define OFF_ALO 10240
#define OFF_BHI 20480
#define OFF_BLO 30720
#define MM_SMEM 67584   // max(40960 mainloop, 128*132*4 epilogue)

template <int EPI>
__global__ __launch_bounds__(256, 2)
void mma_gemm(const float* __restrict__ A,
              const __nv_bfloat16* __restrict__ Whi,
              const __nv_bfloat16* __restrict__ Wlo,
              const float* __restrict__ bias, float* __restrict__ C,
              const int* __restrict__ src, const int* __restrict__ dst,
              const float* __restrict__ Tg)
{
    extern __shared__ char dsm[];
    const uint32_t sbase = smem_u32(dsm);

    const int tid  = threadIdx.x;
    const int wid  = tid >> 5;
    const int lane = tid & 31;
    const int row0 = blockIdx.y * 128;
    const int col0 = blockIdx.x * 128;

    const int wm = wid & 3;          // warp row  (32 rows each)
    const int wn = wid >> 2;         // warp col  (64 cols each)

    // loader mapping: thread handles row lrow, 16-float half lhalf
    const int lrow  = tid >> 1;
    const int lhalf = tid & 1;

    float c[2][8][4];
#pragma unroll
    for (int mt = 0; mt < 2; mt++)
#pragma unroll
        for (int nt = 0; nt < 8; nt++)
#pragma unroll
            for (int q = 0; q < 4; q++) c[mt][nt][q] = 0.f;

    // per-warp fragment smem addresses (lane-dependent part)
    const uint32_t frag_r = (uint32_t)(lane & 15);
    const uint32_t frag_c = (uint32_t)((lane >> 4) << 3);

    for (int kc = 0; kc < 8; kc++) {
        const int k0 = kc * 32 + lhalf * 16;

        // ---- global loads (before sync, overlap with previous compute tail) ----
        const float* ap = A + (size_t)(row0 + lrow) * 256 + k0;
        float4 va0 = *(const float4*)(ap + 0);
        float4 va1 = *(const float4*)(ap + 4);
        float4 va2 = *(const float4*)(ap + 8);
        float4 va3 = *(const float4*)(ap + 12);
        const uint4* whp = (const uint4*)(Whi + (size_t)(col0 + lrow) * 256 + k0);
        const uint4* wlp = (const uint4*)(Wlo + (size_t)(col0 + lrow) * 256 + k0);
        uint4 wh0 = whp[0], wh1 = whp[1];
        uint4 wl0 = wlp[0], wl1 = wlp[1];

        __syncthreads();   // previous chunk's compute done before overwriting smem

        // ---- convert A to bf16 hi/lo and store; store weights ----
        {
            float xs[16];
            xs[0] = va0.x; xs[1] = va0.y; xs[2]  = va0.z; xs[3]  = va0.w;
            xs[4] = va1.x; xs[5] = va1.y; xs[6]  = va1.z; xs[7]  = va1.w;
            xs[8] = va2.x; xs[9] = va2.y; xs[10] = va2.z; xs[11] = va2.w;
            xs[12] = va3.x; xs[13] = va3.y; xs[14] = va3.z; xs[15] = va3.w;
            union { __nv_bfloat16 b[16]; uint4 u[2]; } Uh, Ul;
#pragma unroll
            for (int j = 0; j < 16; j++) {
                __nv_bfloat16 h = __float2bfloat16_rn(xs[j]);
                Uh.b[j] = h;
                Ul.b[j] = __float2bfloat16_rn(xs[j] - __bfloat162float(h));
            }
            char* arow = dsm + lrow * 80 + lhalf * 32;
            *(uint4*)(arow + OFF_AHI)      = Uh.u[0];
            *(uint4*)(arow + OFF_AHI + 16) = Uh.u[1];
            *(uint4*)(arow + OFF_ALO)      = Ul.u[0];
            *(uint4*)(arow + OFF_ALO + 16) = Ul.u[1];
            *(uint4*)(arow + OFF_BHI)      = wh0;
            *(uint4*)(arow + OFF_BHI + 16) = wh1;
            *(uint4*)(arow + OFF_BLO)      = wl0;
            *(uint4*)(arow + OFF_BLO + 16) = wl1;
        }
        __syncthreads();

        // ---- compute: 2 k16 steps ----
#pragma unroll
        for (int ks = 0; ks < 2; ks++) {
            const uint32_t kk = (uint32_t)(ks * 16) + frag_c;
            uint32_t ah[2][4], al[2][4];
#pragma unroll
            for (int mt = 0; mt < 2; mt++) {
                uint32_t ra = (uint32_t)(wm * 32 + mt * 16) + frag_r;
                uint32_t aaddr = sbase + ra * 80 + kk * 2;
                LDSM4(ah[mt][0], ah[mt][1], ah[mt][2], ah[mt][3], aaddr + OFF_AHI);
                LDSM4(al[mt][0], al[mt][1], al[mt][2], al[mt][3], aaddr + OFF_ALO);
            }
#pragma unroll
            for (int p = 0; p < 4; p++) {
                uint32_t rb = (uint32_t)(wn * 64 + p * 16) + frag_r;
                uint32_t baddr = sbase + rb * 80 + kk * 2;
                uint32_t bh[4], bl[4];
                LDSM4(bh[0], bh[1], bh[2], bh[3], baddr + OFF_BHI);
                LDSM4(bl[0], bl[1], bl[2], bl[3], baddr + OFF_BLO);
#pragma unroll
                for (int mt = 0; mt < 2; mt++) {
                    MMA_BF16(c[mt][2 * p],     ah[mt][0], ah[mt][1], ah[mt][2], ah[mt][3], bh[0], bh[2]);
                    MMA_BF16(c[mt][2 * p],     ah[mt][0], ah[mt][1], ah[mt][2], ah[mt][3], bl[0], bl[2]);
                    MMA_BF16(c[mt][2 * p],     al[mt][0], al[mt][1], al[mt][2], al[mt][3], bh[0], bh[2]);
                    MMA_BF16(c[mt][2 * p + 1], ah[mt][0], ah[mt][1], ah[mt][2], ah[mt][3], bh[1], bh[3]);
                    MMA_BF16(c[mt][2 * p + 1], ah[mt][0], ah[mt][1], ah[mt][2], ah[mt][3], bl[1], bl[3]);
                    MMA_BF16(c[mt][2 * p + 1], al[mt][0], al[mt][1], al[mt][2], al[mt][3], bh[1], bh[3]);
                }
            }
        }
    }

    // ---- stage C through smem ----
    __syncthreads();
    float* Csm = (float*)dsm;
    {
        int fr = lane >> 2;
        int fc = (lane & 3) * 2;
#pragma unroll
        for (int mt = 0; mt < 2; mt++) {
#pragma unroll
            for (int nt = 0; nt < 8; nt++) {
                int r = wm * 32 + mt * 16 + fr;
                int col = wn * 64 + nt * 8 + fc;
                *(float2*)&Csm[r * 132 + col]       = make_float2(c[mt][nt][0], c[mt][nt][1]);
                *(float2*)&Csm[(r + 8) * 132 + col] = make_float2(c[mt][nt][2], c[mt][nt][3]);
            }
        }
    }
    __syncthreads();

    // ---- final epilogue: thread handles row lrow, 64-col half ----
    {
        const int row  = lrow;
        const int coff = lhalf * 64;
        const float* crow = Csm + row * 132 + coff;
        const int grow = row0 + row;
        const int gc0  = col0 + coff;

        if (EPI == 2) {
            float* cp = C + (size_t)grow * 256 + gc0;
#pragma unroll
            for (int j = 0; j < 16; j++)
                *(float4*)(cp + 4 * j) = *(const float4*)(crow + 4 * j);
        } else if (EPI == 0) {
            float* cp = C + (size_t)grow * 256 + gc0;
            const float* bp = bias + gc0;
#pragma unroll
            for (int j = 0; j < 16; j++) {
                float4 v = *(const float4*)(crow + 4 * j);
                float4 bv = *(const float4*)(bp + 4 * j);
                float4 o;
                o.x = fmaxf(v.x + bv.x, 0.f);
                o.y = fmaxf(v.y + bv.y, 0.f);
                o.z = fmaxf(v.z + bv.z, 0.f);
                o.w = fmaxf(v.w + bv.w, 0.f);
                *(float4*)(cp + 4 * j) = o;
            }
        } else { // EPI == 3
            int sr = src[grow];
            int dn = dst[grow];
            const float* tp = Tg + (size_t)sr * 256 + gc0;
            const float* bp = bias + gc0;
            float* base = C + (size_t)dn * 256 + gc0;
#pragma unroll
            for (int j = 0; j < 16; j++) {
                float4 a = *(const float4*)(crow + 4 * j);
                float4 tv = *(const float4*)(tp + 4 * j);
                float4 bv = *(const float4*)(bp + 4 * j);
                float4 v;
                v.x = fmaxf(a.x + bv.x + tv.x, 0.f);
                v.y = fmaxf(a.y + bv.y + tv.y, 0.f);
                v.z = fmaxf(a.z + bv.z + tv.z, 0.f);
                v.w = fmaxf(a.w + bv.w + tv.w, 0.f);
                atomicAdd((float4*)(base + 4 * j), v);
            }
        }
    }
}

// ---------------- weight transpose + bf16 split (once per launch) ----------------
__global__ void transp_split(const float* __restrict__ Wm, const float* __restrict__ Wu)
{
    __shared__ float tile[32][33];
    int m = blockIdx.z;
    const float* W = (m < 8)
        ? (Wm + (size_t)(m & 3) * 512 * 256 + (size_t)(m >> 2) * 256 * 256)
        : (Wu + (size_t)(m - 8) * 256 * 256);
    int kx = blockIdx.x * 32;
    int nx = blockIdx.y * 32;
    int tx = threadIdx.x, ty = threadIdx.y;   // 32 x 8
#pragma unroll
    for (int i = 0; i < 4; i++)
        tile[ty + i * 8][tx] = W[(size_t)(kx + ty + i * 8) * 256 + nx + tx];
    __syncthreads();
#pragma unroll
    for (int i = 0; i < 4; i++) {
        float v = tile[tx][ty + i * 8];
        __nv_bfloat16 h = __float2bfloat16_rn(v);
        __nv_bfloat16 l = __float2bfloat16_rn(v - __bfloat162float(h));
        size_t o = (size_t)m * 65536 + (size_t)(nx + ty + i * 8) * 256 + kx + tx;
        g_wThi[o] = h;
        g_wTlo[o] = l;
    }
}

// ---------------- fp32 f32x2 SGEMM for ragged-K embeddings ----------------
#define DUP2(d, f)    asm("mov.b64 %0, {%1, %1};" : "=l"(d) : "f"(f))
#define FMA2(c, a, b) asm("fma.rn.f32x2 %0, %1, %2, %0;" : "+l"(c) : "l"(a), "l"(b))
#define UNPK2(lo, hi, v) asm("mov.b64 {%0, %1}, %2;" : "=f"(lo), "=f"(hi) : "l"(v))

__global__ __launch_bounds__(256, 2)
void gemm_emb(const float* __restrict__ A, int lda, int K,
              const float* __restrict__ Bw,
              const float* __restrict__ bias,
              float* __restrict__ C)
{
    __shared__ float As[2][8][128];
    __shared__ float Bs[2][8][128];

    const int tid  = threadIdx.x;
    const int row0 = blockIdx.y * 128;
    const int col0 = blockIdx.x * 128;

    const int aRow = tid >> 1;
    const int aCol = (tid & 1) << 2;
    const int bRow = tid >> 5;
    const int bCol = (tid & 31) << 2;

    auto load_a = [&](int kt) -> float4 {
        float t0 = 0.f, t1 = 0.f, t2 = 0.f, t3 = 0.f;
        const float* arow = A + (size_t)(row0 + aRow) * lda;
        int k0 = kt + aCol;
        if (k0 + 0 < K) t0 = arow[k0 + 0];
        if (k0 + 1 < K) t1 = arow[k0 + 1];
        if (k0 + 2 < K) t2 = arow[k0 + 2];
        if (k0 + 3 < K) t3 = arow[k0 + 3];
        return make_float4(t0, t1, t2, t3);
    };
    auto load_b = [&](int kt) -> float4 {
        int kb = kt + bRow;
        if (kb >= K) return make_float4(0.f, 0.f, 0.f, 0.f);
        return *(const float4*)(Bw + (size_t)kb * 256 + col0 + bCol);
    };
    auto store_tile = [&](int p, float4 a4, float4 b4) {
        As[p][aCol + 0][aRow] = a4.x;
        As[p][aCol + 1][aRow] = a4.y;
        As[p][aCol + 2][aRow] = a4.z;
        As[p][aCol + 3][aRow] = a4.w;
        *(float4*)&Bs[p][bRow][bCol] = b4;
    };

    unsigned long long acc2[4][8];
#pragma unroll
    for (int i2 = 0; i2 < 4; i2++)
#pragma unroll
        for (int j = 0; j < 8; j++) acc2[i2][j] = 0ULL;

    const int tx = tid & 15;
    const int ty = tid >> 4;

    auto compute = [&](int p) {
#pragma unroll
        for (int kk = 0; kk < 8; kk++) {
            ulonglong2 aA = *(const ulonglong2*)&As[p][kk][ty * 4];
            ulonglong2 aB = *(const ulonglong2*)&As[p][kk][64 + ty * 4];
            unsigned long long a2[4] = {aA.x, aA.y, aB.x, aB.y};
            float4 b0 = *(const float4*)&Bs[p][kk][tx * 4];
            float4 b1 = *(const float4*)&Bs[p][kk][64 + tx * 4];
            unsigned long long bb2[8];
            DUP2(bb2[0], b0.x); DUP2(bb2[1], b0.y); DUP2(bb2[2], b0.z); DUP2(bb2[3], b0.w);
            DUP2(bb2[4], b1.x); DUP2(bb2[5], b1.y); DUP2(bb2[6], b1.z); DUP2(bb2[7], b1.w);
#pragma unroll
            for (int i2 = 0; i2 < 4; i2++)
#pragma unroll
                for (int j = 0; j < 8; j++)
                    FMA2(acc2[i2][j], a2[i2], bb2[j]);
        }
    };

    store_tile(0, load_a(0), load_b(0));
    __syncthreads();
    int p = 0;
    for (int kt = 8; kt < K; kt += 8) {
        float4 a4 = load_a(kt);
        float4 b4 = load_b(kt);
        compute(p);
        store_tile(p ^ 1, a4, b4);
        __syncthreads();
        p ^= 1;
    }
    compute(p);

    float acc[8][8];
#pragma unroll
    for (int i2 = 0; i2 < 4; i2++)
#pragma unroll
        for (int j = 0; j < 8; j++)
            UNPK2(acc[2 * i2][j], acc[2 * i2 + 1][j], acc2[i2][j]);

    float bb[8];
#pragma unroll
    for (int j = 0; j < 4; j++) {
        bb[j]     = bias[col0 + tx * 4 + j];
        bb[4 + j] = bias[col0 + 64 + tx * 4 + j];
    }
#pragma unroll
    for (int i = 0; i < 8; i++) {
        int lrow = (i < 4) ? (ty * 4 + i) : (64 + ty * 4 + (i - 4));
        float* cp = C + (size_t)(row0 + lrow) * 256 + col0;
        float4 o0, o1;
        o0.x = fmaxf(acc[i][0] + bb[0], 0.f);
        o0.y = fmaxf(acc[i][1] + bb[1], 0.f);
        o0.z = fmaxf(acc[i][2] + bb[2], 0.f);
        o0.w = fmaxf(acc[i][3] + bb[3], 0.f);
        o1.x = fmaxf(acc[i][4] + bb[4], 0.f);
        o1.y = fmaxf(acc[i][5] + bb[5], 0.f);
        o1.z = fmaxf(acc[i][6] + bb[6], 0.f);
        o1.w = fmaxf(acc[i][7] + bb[7], 0.f);
        *(float4*)(cp + tx * 4)      = o0;
        *(float4*)(cp + 64 + tx * 4) = o1;
    }
}

// ---------------- LayerNorm: h = LN(h + u, g, b), warp per row ----------------
__global__ void ln_kernel(const float* __restrict__ u,
                          const float* __restrict__ lg,
                          const float* __restrict__ lb)
{
    int row  = blockIdx.x * 8 + (threadIdx.x >> 5);
    int lane = threadIdx.x & 31;
    float*       hrow = g_h + (size_t)row * 256;
    const float* urow = u   + (size_t)row * 256;

    float x[8];
    float4 h0 = *(const float4*)(hrow + lane * 4);
    float4 h1 = *(const float4*)(hrow + 128 + lane * 4);
    float4 u0 = *(const float4*)(urow + lane * 4);
    float4 u1 = *(const float4*)(urow + 128 + lane * 4);
    x[0] = h0.x + u0.x; x[1] = h0.y + u0.y; x[2] = h0.z + u0.z; x[3] = h0.w + u0.w;
    x[4] = h1.x + u1.x; x[5] = h1.y + u1.y; x[6] = h1.z + u1.z; x[7] = h1.w + u1.w;

    float s = 0.f, q = 0.f;
#pragma unroll
    for (int j = 0; j < 8; j++) { s += x[j]; q += x[j] * x[j]; }
#pragma unroll
    for (int o = 16; o > 0; o >>= 1) {
        s += __shfl_xor_sync(0xFFFFFFFFu, s, o);
        q += __shfl_xor_sync(0xFFFFFFFFu, q, o);
    }
    float mu  = s * (1.f / 256.f);
    float var = q * (1.f / 256.f) - mu * mu;
    float rs  = rsqrtf(var + 1e-5f);

    float4 g0 = *(const float4*)(lg + lane * 4);
    float4 g1 = *(const float4*)(lg + 128 + lane * 4);
    float4 b0 = *(const float4*)(lb + lane * 4);
    float4 b1 = *(const float4*)(lb + 128 + lane * 4);

    float4 y0, y1;
    y0.x = (x[0] - mu) * rs * g0.x + b0.x;
    y0.y = (x[1] - mu) * rs * g0.y + b0.y;
    y0.z = (x[2] - mu) * rs * g0.z + b0.z;
    y0.w = (x[3] - mu) * rs * g0.w + b0.w;
    y1.x = (x[4] - mu) * rs * g1.x + b1.x;
    y1.y = (x[5] - mu) * rs * g1.y + b1.y;
    y1.z = (x[6] - mu) * rs * g1.z + b1.z;
    y1.w = (x[7] - mu) * rs * g1.w + b1.w;
    *(float4*)(hrow + lane * 4)       = y0;
    *(float4*)(hrow + 128 + lane * 4) = y1;
}

// ---------------- segment starts from sorted b ----------------
__global__ void seg_starts(const int* __restrict__ b)
{
    int i = blockIdx.x * blockDim.x + threadIdx.x;
    if (i >= NN) return;
    int cur = b[i];
    if (i == 0) {
        for (int g = 0; g <= cur; g++) g_starts[g] = 0;
    } else {
        int prev = b[i - 1];
        if (prev != cur)
            for (int g = prev + 1; g <= cur; g++) g_starts[g] = i;
    }
    if (i == NN - 1)
        for (int g = cur + 1; g <= BBG; g++) g_starts[g] = NN;
}

// ---------------- readout: mean || max per graph ----------------
__global__ void readout_kernel(void)
{
    int g = blockIdx.x;
    int s = g_starts[g], en = g_starts[g + 1];
    int c = threadIdx.x;
    float sum = 0.f, mx = -INFINITY;
    for (int r = s; r < en; r++) {
        float v = g_h[(size_t)r * 256 + c];
        sum += v;
        mx = fmaxf(mx, v);
    }
    int   cnt   = en - s;
    float denom = (cnt > 0) ? (float)cnt : 1.f;
    g_gout[(size_t)g * 512 + c]       = sum / denom;
    g_gout[(size_t)g * 512 + 256 + c] = (cnt > 0) ? mx : 0.f;
}

// ---------------- FiLM + predictor, 8 graphs per block ----------------
__global__ __launch_bounds__(256)
void film_pred(const float* __restrict__ ctx, const int* __restrict__ pid,
               const float* __restrict__ gW1, const float* __restrict__ gb1,
               const float* __restrict__ glng, const float* __restrict__ glnb,
               const float* __restrict__ gW2, const float* __restrict__ gb2,
               const float* __restrict__ bW1, const float* __restrict__ bb1,
               const float* __restrict__ blng, const float* __restrict__ blnb,
               const float* __restrict__ bW2, const float* __restrict__ bb2,
               const float* __restrict__ pW1, const float* __restrict__ pb1,
               const float* __restrict__ pW2, const float* __restrict__ pb2,
               float* __restrict__ out)
{
    __shared__ float s_c[8][128];
    __shared__ float s_t[8][256];
    __shared__ float s_hmod[8][512];

    int tid = threadIdx.x;
    int g0  = blockIdx.x * 8;

    for (int i = tid; i < 8 * 128; i += 256) {
        int r = i >> 7, k = i & 127;
        s_c[r][k] = ctx[(size_t)pid[g0 + r] * 128 + k];
    }
    __syncthreads();

#pragma unroll
    for (int net = 0; net < 2; net++) {
        const float* W1 = net ? bW1 : gW1;
        const float* B1 = net ? bb1 : gb1;
        const float* LG = net ? blng : glng;
        const float* LB = net ? blnb : glnb;
        const float* W2 = net ? bW2 : gW2;
        const float* B2 = net ? bb2 : gb2;

        float a1[8];
#pragma unroll
        for (int r = 0; r < 8; r++) a1[r] = B1[tid];
        for (int k = 0; k < 128; k++) {
            float w = W1[k * 256 + tid];
#pragma unroll
            for (int r = 0; r < 8; r++) a1[r] += s_c[r][k] * w;
        }
#pragma unroll
        for (int r = 0; r < 8; r++) s_t[r][tid] = a1[r];
        __syncthreads();

        {
            int r = tid >> 5, lane = tid & 31;
            float x[8], s = 0.f, q = 0.f;
#pragma unroll
            for (int j = 0; j < 8; j++) {
                x[j] = s_t[r][lane + 32 * j];
                s += x[j]; q += x[j] * x[j];
            }
#pragma unroll
            for (int o = 16; o > 0; o >>= 1) {
                s += __shfl_xor_sync(0xFFFFFFFFu, s, o);
                q += __shfl_xor_sync(0xFFFFFFFFu, q, o);
            }
            float mu  = s * (1.f / 256.f);
            float var = q * (1.f / 256.f) - mu * mu;
            float rs  = rsqrtf(var + 1e-5f);
#pragma unroll
            for (int j = 0; j < 8; j++) {
                int cc = lane + 32 * j;
                float y = (x[j] - mu) * rs * LG[cc] + LB[cc];
                s_t[r][cc] = fmaxf(y, 0.f);
            }
        }
        __syncthreads();

        float a20[8], a21[8];
#pragma unroll
        for (int r = 0; r < 8; r++) { a20[r] = 0.f; a21[r] = 0.f; }
        for (int k = 0; k < 256; k++) {
            float w0 = W2[k * 512 + tid];
            float w1 = W2[k * 512 + tid + 256];
#pragma unroll
            for (int r = 0; r < 8; r++) {
                float t = s_t[r][k];
                a20[r] += t * w0;
                a21[r] += t * w1;
            }
        }
        float bc0 = B2[tid], bc1 = B2[tid + 256];
        if (net == 0) {
#pragma unroll
            for (int r = 0; r < 8; r++) {
                s_hmod[r][tid]       = (a20[r] + bc0) * g_gout[(size_t)(g0 + r) * 512 + tid];
                s_hmod[r][tid + 256] = (a21[r] + bc1) * g_gout[(size_t)(g0 + r) * 512 + tid + 256];
            }
        } else {
#pragma unroll
            for (int r = 0; r < 8; r++) {
                s_hmod[r][tid]       += a20[r] + bc0;
                s_hmod[r][tid + 256] += a21[r] + bc1;
            }
        }
        __syncthreads();
    }

    float az[8];
#pragma unroll
    for (int r = 0; r < 8; r++) az[r] = pb1[tid];
    for (int k = 0; k < 512; k++) {
        float w = pW1[k * 256 + tid];
#pragma unroll
        for (int r = 0; r < 8; r++) az[r] += s_hmod[r][k] * w;
    }
#pragma unroll
    for (int r = 0; r < 8; r++) s_t[r][tid] = fmaxf(az[r], 0.f);
    __syncthreads();

    {
        int r = tid >> 5, lane = tid & 31;
        float p = 0.f;
#pragma unroll
        for (int j = 0; j < 8; j++) {
            int cc = lane + 32 * j;
            p += s_t[r][cc] * pW2[cc];
        }
#pragma unroll
        for (int o = 16; o > 0; o >>= 1) p += __shfl_xor_sync(0xFFFFFFFFu, p, o);
        if (lane == 0) out[g0 + r] = p + pb2[0];
    }
}

// ---------------- host launcher ----------------
extern "C" void kernel_launch(void* const* d_in, const int* in_sizes, int n_in,
                              void* d_out, int out_size)
{
    (void)in_sizes; (void)n_in; (void)out_size;

    const float* nf   = (const float*)d_in[0];
    const int*   ei   = (const int*)  d_in[1];
    const float* ef   = (const float*)d_in[2];
    const int*   bseg = (const int*)  d_in[3];
    const int*   pid  = (const int*)  d_in[4];
    const float* Wn   = (const float*)d_in[5];
    const float* bn   = (const float*)d_in[6];
    const float* We   = (const float*)d_in[7];
    const float* be   = (const float*)d_in[8];
    const float* Wm   = (const float*)d_in[9];
    const float* bm   = (const float*)d_in[10];
    const float* Wu   = (const float*)d_in[11];
    const float* bu   = (const float*)d_in[12];
    const float* lng  = (const float*)d_in[13];
    const float* lnb  = (const float*)d_in[14];
    const float* ctx  = (const float*)d_in[15];
    const float* gW1  = (const float*)d_in[16];
    const float* gb1  = (const float*)d_in[17];
    const float* glng = (const float*)d_in[18];
    const float* glnb = (const float*)d_in[19];
    const float* gW2  = (const float*)d_in[20];
    const float* gb2  = (const float*)d_in[21];
    const float* bW1  = (const float*)d_in[22];
    const float* bb1  = (const float*)d_in[23];
    const float* blng = (const float*)d_in[24];
    const float* blnb = (const float*)d_in[25];
    const float* bW2  = (const float*)d_in[26];
    const float* bb2  = (const float*)d_in[27];
    const float* pW1  = (const float*)d_in[28];
    const float* pb1  = (const float*)d_in[29];
    const float* pW2  = (const float*)d_in[30];
    const float* pb2  = (const float*)d_in[31];
    float* out = (float*)d_out;

    const int* src = ei;
    const int* dst = ei + EE;

    float *h_ptr, *e_ptr, *agg_ptr, *u_ptr, *t_ptr;
    __nv_bfloat16 *wThi, *wTlo;
    cudaGetSymbolAddress((void**)&h_ptr,   g_h);
    cudaGetSymbolAddress((void**)&e_ptr,   g_e);
    cudaGetSymbolAddress((void**)&agg_ptr, g_agg);
    cudaGetSymbolAddress((void**)&u_ptr,   g_u);
    cudaGetSymbolAddress((void**)&t_ptr,   g_t);
    cudaGetSymbolAddress((void**)&wThi,    g_wThi);
    cudaGetSymbolAddress((void**)&wTlo,    g_wTlo);

    cudaFuncSetAttribute(mma_gemm<0>, cudaFuncAttributeMaxDynamicSharedMemorySize, MM_SMEM);
    cudaFuncSetAttribute(mma_gemm<2>, cudaFuncAttributeMaxDynamicSharedMemorySize, MM_SMEM);
    cudaFuncSetAttribute(mma_gemm<3>, cudaFuncAttributeMaxDynamicSharedMemorySize, MM_SMEM);

    dim3 thr(256);

    // weight transpose + bf16 split
    transp_split<<<dim3(8, 8, 12), dim3(32, 8)>>>(Wm, Wu);

    // input embeddings (ragged K, fp32 path)
    gemm_emb<<<dim3(2, NN / 128), thr>>>(nf, 69, 69, Wn, bn, h_ptr);
    gemm_emb<<<dim3(2, EE / 128), thr>>>(ef, 9, 9, We, be, e_ptr);

    // MPNN layers (mma.sync bf16x3)
    for (int l = 0; l < LLAY; l++) {
        const __nv_bfloat16* topHi = wThi + (size_t)l * 65536;
        const __nv_bfloat16* topLo = wTlo + (size_t)l * 65536;
        const __nv_bfloat16* botHi = wThi + (size_t)(4 + l) * 65536;
        const __nv_bfloat16* botLo = wTlo + (size_t)(4 + l) * 65536;
        const __nv_bfloat16* wuHi  = wThi + (size_t)(8 + l) * 65536;
        const __nv_bfloat16* wuLo  = wTlo + (size_t)(8 + l) * 65536;

        cudaMemsetAsync(agg_ptr, 0, (size_t)NN * HIDD * sizeof(float), 0);

        // t = h @ Wm_top
        mma_gemm<2><<<dim3(2, NN / 128), thr, MM_SMEM>>>(
            h_ptr, topHi, topLo, nullptr, t_ptr, nullptr, nullptr, nullptr);

        // agg[dst] += relu(e @ Wm_bot + bm + t[src])
        mma_gemm<3><<<dim3(2, EE / 128), thr, MM_SMEM>>>(
            e_ptr, botHi, botLo, bm + (size_t)l * 256, agg_ptr, src, dst, t_ptr);

        // u = relu(agg @ Wu + bu)
        mma_gemm<0><<<dim3(2, NN / 128), thr, MM_SMEM>>>(
            agg_ptr, wuHi, wuLo, bu + (size_t)l * 256, u_ptr, nullptr, nullptr, nullptr);

        // h = LN(h + u)
        ln_kernel<<<NN / 8, 256>>>(u_ptr, lng + (size_t)l * 256, lnb + (size_t)l * 256);
    }

    // readout + FiLM + predictor
    seg_starts<<<NN / 256, 256>>>(bseg);
    readout_kernel<<<BBG, 256>>>();
    film_pred<<<BBG / 8, 256>>>(ctx, pid,
                                gW1, gb1, glng, glnb, gW2, gb2,
                                bW1, bb1, blng, blnb, bW2, bb2,
                                pW1, pb1, pW2, pb2, out);
}

// round 10
// speedup vs baseline: 2.2288x; 1.0386x over previous
#include <cuda_runtime.h>
#include <cuda_bf16.h>
#include <math.h>
#include <stdint.h>

#define NN   131072
#define EE   262144
#define BBG  4096
#define HIDD 256
#define LLAY 4

// ---------------- scratch (device globals; no allocation) ----------------
__device__ float g_h[(size_t)NN * HIDD];
__device__ float g_e[(size_t)EE * HIDD];
__device__ float g_agg[(size_t)NN * HIDD];
__device__ float g_u[(size_t)NN * HIDD];
__device__ float g_t[(size_t)NN * HIDD];
__device__ float g_gout[(size_t)BBG * 512];
__device__ int   g_starts[BBG + 1];
// transposed + bf16-split weights: 12 matrices of [256(n)][256(k)] bf16
__device__ __nv_bfloat16 g_wThi[12 * 256 * 256];
__device__ __nv_bfloat16 g_wTlo[12 * 256 * 256];

// ---------------- PTX helpers ----------------
__device__ __forceinline__ uint32_t smem_u32(const void* p) {
    uint32_t a;
    asm("{ .reg .u64 t; cvta.to.shared.u64 t, %1; cvt.u32.u64 %0, t; }" : "=r"(a) : "l"(p));
    return a;
}
#define LDSM4(r0, r1, r2, r3, addr) \
    asm volatile("ldmatrix.sync.aligned.m8n8.x4.shared.b16 {%0,%1,%2,%3}, [%4];" \
        : "=r"(r0), "=r"(r1), "=r"(r2), "=r"(r3) : "r"(addr))
#define MMA_BF16(c, a0, a1, a2, a3, b0, b1) \
    asm volatile("mma.sync.aligned.m16n8k16.row.col.f32.bf16.bf16.f32 " \
        "{%0,%1,%2,%3}, {%4,%5,%6,%7}, {%8,%9}, {%0,%1,%2,%3};" \
        : "+f"((c)[0]), "+f"((c)[1]), "+f"((c)[2]), "+f"((c)[3]) \
        : "r"(a0), "r"(a1), "r"(a2), "r"(a3), "r"(b0), "r"(b1))
#define CP_ASYNC16(dst, srcp) \
    asm volatile("cp.async.cg.shared.global [%0], [%1], 16;" :: "r"(dst), "l"(srcp) : "memory")
#define CP_COMMIT() asm volatile("cp.async.commit_group;" ::: "memory")
#define CP_WAIT0()  asm volatile("cp.async.wait_group 0;" ::: "memory")

// ---------------- mma.sync bf16x3 GEMM: C[M,256] = A[M,256] @ WT^T ----------------
// 128x128 C tile/CTA, 8 warps 4(m)x2(n), warp tile 32x64.
// Double-buffered smem chunks (128 rows x 32 bf16, 80B row stride, conflict-free).
// Weights arrive via cp.async.cg (L1-bypass); A converted fp32->bf16 hi/lo in regs.
// EPI 0: C=relu(acc+bias)  EPI 2: C=acc  EPI 3: agg[dst] +=RED relu(acc+bias+Tg[src])
#define OFF_AHI 0
#define OFF_ALO 10240
#define OFF_BHI 20480
#define OFF_BLO 30720
#define BUFSZ   40960
#define MM_SMEM 81920   // 2 buffers; epilogue staging (128*132*4=67584) aliases them

template <int EPI>
__global__ __launch_bounds__(256, 2)
void mma_gemm(const float* __restrict__ A,
              const __nv_bfloat16* __restrict__ Whi,
              const __nv_bfloat16* __restrict__ Wlo,
              const float* __restrict__ bias, float* __restrict__ C,
              const int* __restrict__ src, const int* __restrict__ dst,
              const float* __restrict__ Tg)
{
    extern __shared__ char dsm[];
    const uint32_t sbase = smem_u32(dsm);

    const int tid  = threadIdx.x;
    const int wid  = tid >> 5;
    const int lane = tid & 31;
    const int row0 = blockIdx.y * 128;
    const int col0 = blockIdx.x * 128;

    const int wm = wid & 3;          // warp row (32 rows)
    const int wn = wid >> 2;         // warp col (64 cols)

    const int lrow  = tid >> 1;      // loader row 0..127
    const int lhalf = tid & 1;       // 16-element half

    float c[2][8][4];
#pragma unroll
    for (int mt = 0; mt < 2; mt++)
#pragma unroll
        for (int nt = 0; nt < 8; nt++)
#pragma unroll
            for (int q = 0; q < 4; q++) c[mt][nt][q] = 0.f;

    const uint32_t frag_r = (uint32_t)(lane & 15);
    const uint32_t frag_c = (uint32_t)((lane >> 4) << 3);

    // issue cp.async for weight tile of chunk kc into buffer b
    auto ldw_async = [&](int kc, int b) {
        uint32_t drow = sbase + b * BUFSZ + lrow * 80 + lhalf * 32;
        const char* wh = (const char*)(Whi + (size_t)(col0 + lrow) * 256 + kc * 32 + lhalf * 16);
        const char* wl = (const char*)(Wlo + (size_t)(col0 + lrow) * 256 + kc * 32 + lhalf * 16);
        CP_ASYNC16(drow + OFF_BHI,      wh);
        CP_ASYNC16(drow + OFF_BHI + 16, wh + 16);
        CP_ASYNC16(drow + OFF_BLO,      wl);
        CP_ASYNC16(drow + OFF_BLO + 16, wl + 16);
    };
    // load A chunk kc (fp32) into regs
    auto lda = [&](int kc, float4* va) {
        const float* ap = A + (size_t)(row0 + lrow) * 256 + kc * 32 + lhalf * 16;
        va[0] = *(const float4*)(ap + 0);
        va[1] = *(const float4*)(ap + 4);
        va[2] = *(const float4*)(ap + 8);
        va[3] = *(const float4*)(ap + 12);
    };
    // convert + store A into buffer b
    auto sta = [&](int b, const float4* va) {
        float xs[16];
        xs[0] = va[0].x; xs[1] = va[0].y; xs[2]  = va[0].z; xs[3]  = va[0].w;
        xs[4] = va[1].x; xs[5] = va[1].y; xs[6]  = va[1].z; xs[7]  = va[1].w;
        xs[8] = va[2].x; xs[9] = va[2].y; xs[10] = va[2].z; xs[11] = va[2].w;
        xs[12] = va[3].x; xs[13] = va[3].y; xs[14] = va[3].z; xs[15] = va[3].w;
        union { __nv_bfloat16 bb[16]; uint4 u[2]; } Uh, Ul;
#pragma unroll
        for (int j = 0; j < 16; j++) {
            __nv_bfloat16 h = __float2bfloat16_rn(xs[j]);
            Uh.bb[j] = h;
            Ul.bb[j] = __float2bfloat16_rn(xs[j] - __bfloat162float(h));
        }
        char* arow = dsm + b * BUFSZ + lrow * 80 + lhalf * 32;
        *(uint4*)(arow + OFF_AHI)      = Uh.u[0];
        *(uint4*)(arow + OFF_AHI + 16) = Uh.u[1];
        *(uint4*)(arow + OFF_ALO)      = Ul.u[0];
        *(uint4*)(arow + OFF_ALO + 16) = Ul.u[1];
    };

    auto compute = [&](int b) {
        const uint32_t boff = sbase + b * BUFSZ;
#pragma unroll
        for (int ks = 0; ks < 2; ks++) {
            const uint32_t kk = (uint32_t)(ks * 16) + frag_c;
            uint32_t ah[2][4], al[2][4];
#pragma unroll
            for (int mt = 0; mt < 2; mt++) {
                uint32_t ra = (uint32_t)(wm * 32 + mt * 16) + frag_r;
                uint32_t aaddr = boff + ra * 80 + kk * 2;
                LDSM4(ah[mt][0], ah[mt][1], ah[mt][2], ah[mt][3], aaddr + OFF_AHI);
                LDSM4(al[mt][0], al[mt][1], al[mt][2], al[mt][3], aaddr + OFF_ALO);
            }
#pragma unroll
            for (int p = 0; p < 4; p++) {
                uint32_t rb = (uint32_t)(wn * 64 + p * 16) + frag_r;
                uint32_t baddr = boff + rb * 80 + kk * 2;
                uint32_t bh[4], bl[4];
                LDSM4(bh[0], bh[1], bh[2], bh[3], baddr + OFF_BHI);
                LDSM4(bl[0], bl[1], bl[2], bl[3], baddr + OFF_BLO);
#pragma unroll
                for (int mt = 0; mt < 2; mt++) {
                    MMA_BF16(c[mt][2 * p],     ah[mt][0], ah[mt][1], ah[mt][2], ah[mt][3], bh[0], bh[2]);
                    MMA_BF16(c[mt][2 * p],     ah[mt][0], ah[mt][1], ah[mt][2], ah[mt][3], bl[0], bl[2]);
                    MMA_BF16(c[mt][2 * p],     al[mt][0], al[mt][1], al[mt][2], al[mt][3], bh[0], bh[2]);
                    MMA_BF16(c[mt][2 * p + 1], ah[mt][0], ah[mt][1], ah[mt][2], ah[mt][3], bh[1], bh[3]);
                    MMA_BF16(c[mt][2 * p + 1], ah[mt][0], ah[mt][1], ah[mt][2], ah[mt][3], bl[1], bl[3]);
                    MMA_BF16(c[mt][2 * p + 1], al[mt][0], al[mt][1], al[mt][2], al[mt][3], bh[1], bh[3]);
                }
            }
        }
    };

    // ---- prologue: fill buffer 0 with chunk 0 ----
    {
        ldw_async(0, 0);
        CP_COMMIT();
        float4 va0[4];
        lda(0, va0);
        sta(0, va0);
        CP_WAIT0();
    }
    __syncthreads();

    // ---- mainloop: one sync per chunk, double-buffered ----
    for (int kc = 0; kc < 8; kc++) {
        const int buf = kc & 1;
        float4 va[4];
        if (kc < 7) {
            ldw_async(kc + 1, buf ^ 1);   // W(k+1) -> other buffer, async (L1-bypass)
            CP_COMMIT();
            lda(kc + 1, va);              // A(k+1) global loads in flight during compute
        }
        compute(buf);
        if (kc < 7) {
            sta(buf ^ 1, va);             // convert+store A(k+1)
            CP_WAIT0();                   // W(k+1) landed
        }
        __syncthreads();
    }

    // ---- stage C through smem ----
    __syncthreads();
    float* Csm = (float*)dsm;
    {
        int fr = lane >> 2;
        int fc = (lane & 3) * 2;
#pragma unroll
        for (int mt = 0; mt < 2; mt++) {
#pragma unroll
            for (int nt = 0; nt < 8; nt++) {
                int r = wm * 32 + mt * 16 + fr;
                int col = wn * 64 + nt * 8 + fc;
                *(float2*)&Csm[r * 132 + col]       = make_float2(c[mt][nt][0], c[mt][nt][1]);
                *(float2*)&Csm[(r + 8) * 132 + col] = make_float2(c[mt][nt][2], c[mt][nt][3]);
            }
        }
    }
    __syncthreads();

    // ---- final epilogue: thread handles row lrow, 64-col half ----
    {
        const int row  = lrow;
        const int coff = lhalf * 64;
        const float* crow = Csm + row * 132 + coff;
        const int grow = row0 + row;
        const int gc0  = col0 + coff;

        if (EPI == 2) {
            float* cp = C + (size_t)grow * 256 + gc0;
#pragma unroll
            for (int j = 0; j < 16; j++)
                *(float4*)(cp + 4 * j) = *(const float4*)(crow + 4 * j);
        } else if (EPI == 0) {
            float* cp = C + (size_t)grow * 256 + gc0;
            const float* bp = bias + gc0;
#pragma unroll
            for (int j = 0; j < 16; j++) {
                float4 v = *(const float4*)(crow + 4 * j);
                float4 bv = *(const float4*)(bp + 4 * j);
                float4 o;
                o.x = fmaxf(v.x + bv.x, 0.f);
                o.y = fmaxf(v.y + bv.y, 0.f);
                o.z = fmaxf(v.z + bv.z, 0.f);
                o.w = fmaxf(v.w + bv.w, 0.f);
                *(float4*)(cp + 4 * j) = o;
            }
        } else { // EPI == 3
            int sr = src[grow];
            int dn = dst[grow];
            const float* tp = Tg + (size_t)sr * 256 + gc0;
            const float* bp = bias + gc0;
            float* base = C + (size_t)dn * 256 + gc0;
#pragma unroll
            for (int j = 0; j < 16; j++) {
                float4 a = *(const float4*)(crow + 4 * j);
                float4 tv = *(const float4*)(tp + 4 * j);
                float4 bv = *(const float4*)(bp + 4 * j);
                float4 v;
                v.x = fmaxf(a.x + bv.x + tv.x, 0.f);
                v.y = fmaxf(a.y + bv.y + tv.y, 0.f);
                v.z = fmaxf(a.z + bv.z + tv.z, 0.f);
                v.w = fmaxf(a.w + bv.w + tv.w, 0.f);
                atomicAdd((float4*)(base + 4 * j), v);
            }
        }
    }
}

// ---------------- weight transpose + bf16 split (once per launch) ----------------
__global__ void transp_split(const float* __restrict__ Wm, const float* __restrict__ Wu)
{
    __shared__ float tile[32][33];
    int m = blockIdx.z;
    const float* W = (m < 8)
        ? (Wm + (size_t)(m & 3) * 512 * 256 + (size_t)(m >> 2) * 256 * 256)
        : (Wu + (size_t)(m - 8) * 256 * 256);
    int kx = blockIdx.x * 32;
    int nx = blockIdx.y * 32;
    int tx = threadIdx.x, ty = threadIdx.y;   // 32 x 8
#pragma unroll
    for (int i = 0; i < 4; i++)
        tile[ty + i * 8][tx] = W[(size_t)(kx + ty + i * 8) * 256 + nx + tx];
    __syncthreads();
#pragma unroll
    for (int i = 0; i < 4; i++) {
        float v = tile[tx][ty + i * 8];
        __nv_bfloat16 h = __float2bfloat16_rn(v);
        __nv_bfloat16 l = __float2bfloat16_rn(v - __bfloat162float(h));
        size_t o = (size_t)m * 65536 + (size_t)(nx + ty + i * 8) * 256 + kx + tx;
        g_wThi[o] = h;
        g_wTlo[o] = l;
    }
}

// ---------------- fp32 f32x2 SGEMM for ragged-K embeddings ----------------
#define DUP2(d, f)    asm("mov.b64 %0, {%1, %1};" : "=l"(d) : "f"(f))
#define FMA2(c, a, b) asm("fma.rn.f32x2 %0, %1, %2, %0;" : "+l"(c) : "l"(a), "l"(b))
#define UNPK2(lo, hi, v) asm("mov.b64 {%0, %1}, %2;" : "=f"(lo), "=f"(hi) : "l"(v))

__global__ __launch_bounds__(256, 2)
void gemm_emb(const float* __restrict__ A, int lda, int K,
              const float* __restrict__ Bw,
              const float* __restrict__ bias,
              float* __restrict__ C)
{
    __shared__ float As[2][8][128];
    __shared__ float Bs[2][8][128];

    const int tid  = threadIdx.x;
    const int row0 = blockIdx.y * 128;
    const int col0 = blockIdx.x * 128;

    const int aRow = tid >> 1;
    const int aCol = (tid & 1) << 2;
    const int bRow = tid >> 5;
    const int bCol = (tid & 31) << 2;

    auto load_a = [&](int kt) -> float4 {
        float t0 = 0.f, t1 = 0.f, t2 = 0.f, t3 = 0.f;
        const float* arow = A + (size_t)(row0 + aRow) * lda;
        int k0 = kt + aCol;
        if (k0 + 0 < K) t0 = arow[k0 + 0];
        if (k0 + 1 < K) t1 = arow[k0 + 1];
        if (k0 + 2 < K) t2 = arow[k0 + 2];
        if (k0 + 3 < K) t3 = arow[k0 + 3];
        return make_float4(t0, t1, t2, t3);
    };
    auto load_b = [&](int kt) -> float4 {
        int kb = kt + bRow;
        if (kb >= K) return make_float4(0.f, 0.f, 0.f, 0.f);
        return *(const float4*)(Bw + (size_t)kb * 256 + col0 + bCol);
    };
    auto store_tile = [&](int p, float4 a4, float4 b4) {
        As[p][aCol + 0][aRow] = a4.x;
        As[p][aCol + 1][aRow] = a4.y;
        As[p][aCol + 2][aRow] = a4.z;
        As[p][aCol + 3][aRow] = a4.w;
        *(float4*)&Bs[p][bRow][bCol] = b4;
    };

    unsigned long long acc2[4][8];
#pragma unroll
    for (int i2 = 0; i2 < 4; i2++)
#pragma unroll
        for (int j = 0; j < 8; j++) acc2[i2][j] = 0ULL;

    const int tx = tid & 15;
    const int ty = tid >> 4;

    auto compute = [&](int p) {
#pragma unroll
        for (int kk = 0; kk < 8; kk++) {
            ulonglong2 aA = *(const ulonglong2*)&As[p][kk][ty * 4];
            ulonglong2 aB = *(const ulonglong2*)&As[p][kk][64 + ty * 4];
            unsigned long long a2[4] = {aA.x, aA.y, aB.x, aB.y};
            float4 b0 = *(const float4*)&Bs[p][kk][tx * 4];
            float4 b1 = *(const float4*)&Bs[p][kk][64 + tx * 4];
            unsigned long long bb2[8];
            DUP2(bb2[0], b0.x); DUP2(bb2[1], b0.y); DUP2(bb2[2], b0.z); DUP2(bb2[3], b0.w);
            DUP2(bb2[4], b1.x); DUP2(bb2[5], b1.y); DUP2(bb2[6], b1.z); DUP2(bb2[7], b1.w);
#pragma unroll
            for (int i2 = 0; i2 < 4; i2++)
#pragma unroll
                for (int j = 0; j < 8; j++)
                    FMA2(acc2[i2][j], a2[i2], bb2[j]);
        }
    };

    store_tile(0, load_a(0), load_b(0));
    __syncthreads();
    int p = 0;
    for (int kt = 8; kt < K; kt += 8) {
        float4 a4 = load_a(kt);
        float4 b4 = load_b(kt);
        compute(p);
        store_tile(p ^ 1, a4, b4);
        __syncthreads();
        p ^= 1;
    }
    compute(p);

    float acc[8][8];
#pragma unroll
    for (int i2 = 0; i2 < 4; i2++)
#pragma unroll
        for (int j = 0; j < 8; j++)
            UNPK2(acc[2 * i2][j], acc[2 * i2 + 1][j], acc2[i2][j]);

    float bb[8];
#pragma unroll
    for (int j = 0; j < 4; j++) {
        bb[j]     = bias[col0 + tx * 4 + j];
        bb[4 + j] = bias[col0 + 64 + tx * 4 + j];
    }
#pragma unroll
    for (int i = 0; i < 8; i++) {
        int lrow = (i < 4) ? (ty * 4 + i) : (64 + ty * 4 + (i - 4));
        float* cp = C + (size_t)(row0 + lrow) * 256 + col0;
        float4 o0, o1;
        o0.x = fmaxf(acc[i][0] + bb[0], 0.f);
        o0.y = fmaxf(acc[i][1] + bb[1], 0.f);
        o0.z = fmaxf(acc[i][2] + bb[2], 0.f);
        o0.w = fmaxf(acc[i][3] + bb[3], 0.f);
        o1.x = fmaxf(acc[i][4] + bb[4], 0.f);
        o1.y = fmaxf(acc[i][5] + bb[5], 0.f);
        o1.z = fmaxf(acc[i][6] + bb[6], 0.f);
        o1.w = fmaxf(acc[i][7] + bb[7], 0.f);
        *(float4*)(cp + tx * 4)      = o0;
        *(float4*)(cp + 64 + tx * 4) = o1;
    }
}

// ---------------- LayerNorm: h = LN(h + u, g, b), warp per row ----------------
__global__ void ln_kernel(const float* __restrict__ u,
                          const float* __restrict__ lg,
                          const float* __restrict__ lb)
{
    int row  = blockIdx.x * 8 + (threadIdx.x >> 5);
    int lane = threadIdx.x & 31;
    float*       hrow = g_h + (size_t)row * 256;
    const float* urow = u   + (size_t)row * 256;

    float x[8];
    float4 h0 = *(const float4*)(hrow + lane * 4);
    float4 h1 = *(const float4*)(hrow + 128 + lane * 4);
    float4 u0 = *(const float4*)(urow + lane * 4);
    float4 u1 = *(const float4*)(urow + 128 + lane * 4);
    x[0] = h0.x + u0.x; x[1] = h0.y + u0.y; x[2] = h0.z + u0.z; x[3] = h0.w + u0.w;
    x[4] = h1.x + u1.x; x[5] = h1.y + u1.y; x[6] = h1.z + u1.z; x[7] = h1.w + u1.w;

    float s = 0.f, q = 0.f;
#pragma unroll
    for (int j = 0; j < 8; j++) { s += x[j]; q += x[j] * x[j]; }
#pragma unroll
    for (int o = 16; o > 0; o >>= 1) {
        s += __shfl_xor_sync(0xFFFFFFFFu, s, o);
        q += __shfl_xor_sync(0xFFFFFFFFu, q, o);
    }
    float mu  = s * (1.f / 256.f);
    float var = q * (1.f / 256.f) - mu * mu;
    float rs  = rsqrtf(var + 1e-5f);

    float4 g0 = *(const float4*)(lg + lane * 4);
    float4 g1 = *(const float4*)(lg + 128 + lane * 4);
    float4 b0 = *(const float4*)(lb + lane * 4);
    float4 b1 = *(const float4*)(lb + 128 + lane * 4);

    float4 y0, y1;
    y0.x = (x[0] - mu) * rs * g0.x + b0.x;
    y0.y = (x[1] - mu) * rs * g0.y + b0.y;
    y0.z = (x[2] - mu) * rs * g0.z + b0.z;
    y0.w = (x[3] - mu) * rs * g0.w + b0.w;
    y1.x = (x[4] - mu) * rs * g1.x + b1.x;
    y1.y = (x[5] - mu) * rs * g1.y + b1.y;
    y1.z = (x[6] - mu) * rs * g1.z + b1.z;
    y1.w = (x[7] - mu) * rs * g1.w + b1.w;
    *(float4*)(hrow + lane * 4)       = y0;
    *(float4*)(hrow + 128 + lane * 4) = y1;
}

// ---------------- segment starts from sorted b ----------------
__global__ void seg_starts(const int* __restrict__ b)
{
    int i = blockIdx.x * blockDim.x + threadIdx.x;
    if (i >= NN) return;
    int cur = b[i];
    if (i == 0) {
        for (int g = 0; g <= cur; g++) g_starts[g] = 0;
    } else {
        int prev = b[i - 1];
        if (prev != cur)
            for (int g = prev + 1; g <= cur; g++) g_starts[g] = i;
    }
    if (i == NN - 1)
        for (int g = cur + 1; g <= BBG; g++) g_starts[g] = NN;
}

// ---------------- readout: mean || max per graph ----------------
__global__ void readout_kernel(void)
{
    int g = blockIdx.x;
    int s = g_starts[g], en = g_starts[g + 1];
    int c = threadIdx.x;
    float sum = 0.f, mx = -INFINITY;
    for (int r = s; r < en; r++) {
        float v = g_h[(size_t)r * 256 + c];
        sum += v;
        mx = fmaxf(mx, v);
    }
    int   cnt   = en - s;
    float denom = (cnt > 0) ? (float)cnt : 1.f;
    g_gout[(size_t)g * 512 + c]       = sum / denom;
    g_gout[(size_t)g * 512 + 256 + c] = (cnt > 0) ? mx : 0.f;
}

// ---------------- FiLM + predictor, 8 graphs per block ----------------
__global__ __launch_bounds__(256)
void film_pred(const float* __restrict__ ctx, const int* __restrict__ pid,
               const float* __restrict__ gW1, const float* __restrict__ gb1,
               const float* __restrict__ glng, const float* __restrict__ glnb,
               const float* __restrict__ gW2, const float* __restrict__ gb2,
               const float* __restrict__ bW1, const float* __restrict__ bb1,
               const float* __restrict__ blng, const float* __restrict__ blnb,
               const float* __restrict__ bW2, const float* __restrict__ bb2,
               const float* __restrict__ pW1, const float* __restrict__ pb1,
               const float* __restrict__ pW2, const float* __restrict__ pb2,
               float* __restrict__ out)
{
    __shared__ float s_c[8][128];
    __shared__ float s_t[8][256];
    __shared__ float s_hmod[8][512];

    int tid = threadIdx.x;
    int g0  = blockIdx.x * 8;

    for (int i = tid; i < 8 * 128; i += 256) {
        int r = i >> 7, k = i & 127;
        s_c[r][k] = ctx[(size_t)pid[g0 + r] * 128 + k];
    }
    __syncthreads();

#pragma unroll
    for (int net = 0; net < 2; net++) {
        const float* W1 = net ? bW1 : gW1;
        const float* B1 = net ? bb1 : gb1;
        const float* LG = net ? blng : glng;
        const float* LB = net ? blnb : glnb;
        const float* W2 = net ? bW2 : gW2;
        const float* B2 = net ? bb2 : gb2;

        float a1[8];
#pragma unroll
        for (int r = 0; r < 8; r++) a1[r] = B1[tid];
        for (int k = 0; k < 128; k++) {
            float w = W1[k * 256 + tid];
#pragma unroll
            for (int r = 0; r < 8; r++) a1[r] += s_c[r][k] * w;
        }
#pragma unroll
        for (int r = 0; r < 8; r++) s_t[r][tid] = a1[r];
        __syncthreads();

        {
            int r = tid >> 5, lane = tid & 31;
            float x[8], s = 0.f, q = 0.f;
#pragma unroll
            for (int j = 0; j < 8; j++) {
                x[j] = s_t[r][lane + 32 * j];
                s += x[j]; q += x[j] * x[j];
            }
#pragma unroll
            for (int o = 16; o > 0; o >>= 1) {
                s += __shfl_xor_sync(0xFFFFFFFFu, s, o);
                q += __shfl_xor_sync(0xFFFFFFFFu, q, o);
            }
            float mu  = s * (1.f / 256.f);
            float var = q * (1.f / 256.f) - mu * mu;
            float rs  = rsqrtf(var + 1e-5f);
#pragma unroll
            for (int j = 0; j < 8; j++) {
                int cc = lane + 32 * j;
                float y = (x[j] - mu) * rs * LG[cc] + LB[cc];
                s_t[r][cc] = fmaxf(y, 0.f);
            }
        }
        __syncthreads();

        float a20[8], a21[8];
#pragma unroll
        for (int r = 0; r < 8; r++) { a20[r] = 0.f; a21[r] = 0.f; }
        for (int k = 0; k < 256; k++) {
            float w0 = W2[k * 512 + tid];
            float w1 = W2[k * 512 + tid + 256];
#pragma unroll
            for (int r = 0; r < 8; r++) {
                float t = s_t[r][k];
                a20[r] += t * w0;
                a21[r] += t * w1;
            }
        }
        float bc0 = B2[tid], bc1 = B2[tid + 256];
        if (net == 0) {
#pragma unroll
            for (int r = 0; r < 8; r++) {
                s_hmod[r][tid]       = (a20[r] + bc0) * g_gout[(size_t)(g0 + r) * 512 + tid];
                s_hmod[r][tid + 256] = (a21[r] + bc1) * g_gout[(size_t)(g0 + r) * 512 + tid + 256];
            }
        } else {
#pragma unroll
            for (int r = 0; r < 8; r++) {
                s_hmod[r][tid]       += a20[r] + bc0;
                s_hmod[r][tid + 256] += a21[r] + bc1;
            }
        }
        __syncthreads();
    }

    float az[8];
#pragma unroll
    for (int r = 0; r < 8; r++) az[r] = pb1[tid];
    for (int k = 0; k < 512; k++) {
        float w = pW1[k * 256 + tid];
#pragma unroll
        for (int r = 0; r < 8; r++) az[r] += s_hmod[r][k] * w;
    }
#pragma unroll
    for (int r = 0; r < 8; r++) s_t[r][tid] = fmaxf(az[r], 0.f);
    __syncthreads();

    {
        int r = tid >> 5, lane = tid & 31;
        float p = 0.f;
#pragma unroll
        for (int j = 0; j < 8; j++) {
            int cc = lane + 32 * j;
            p += s_t[r][cc] * pW2[cc];
        }
#pragma unroll
        for (int o = 16; o > 0; o >>= 1) p += __shfl_xor_sync(0xFFFFFFFFu, p, o);
        if (lane == 0) out[g0 + r] = p + pb2[0];
    }
}

// ---------------- host launcher ----------------
extern "C" void kernel_launch(void* const* d_in, const int* in_sizes, int n_in,
                              void* d_out, int out_size)
{
    (void)in_sizes; (void)n_in; (void)out_size;

    const float* nf   = (const float*)d_in[0];
    const int*   ei   = (const int*)  d_in[1];
    const float* ef   = (const float*)d_in[2];
    const int*   bseg = (const int*)  d_in[3];
    const int*   pid  = (const int*)  d_in[4];
    const float* Wn   = (const float*)d_in[5];
    const float* bn   = (const float*)d_in[6];
    const float* We   = (const float*)d_in[7];
    const float* be   = (const float*)d_in[8];
    const float* Wm   = (const float*)d_in[9];
    const float* bm   = (const float*)d_in[10];
    const float* Wu   = (const float*)d_in[11];
    const float* bu   = (const float*)d_in[12];
    const float* lng  = (const float*)d_in[13];
    const float* lnb  = (const float*)d_in[14];
    const float* ctx  = (const float*)d_in[15];
    const float* gW1  = (const float*)d_in[16];
    const float* gb1  = (const float*)d_in[17];
    const float* glng = (const float*)d_in[18];
    const float* glnb = (const float*)d_in[19];
    const float* gW2  = (const float*)d_in[20];
    const float* gb2  = (const float*)d_in[21];
    const float* bW1  = (const float*)d_in[22];
    const float* bb1  = (const float*)d_in[23];
    const float* blng = (const float*)d_in[24];
    const float* blnb = (const float*)d_in[25];
    const float* bW2  = (const float*)d_in[26];
    const float* bb2  = (const float*)d_in[27];
    const float* pW1  = (const float*)d_in[28];
    const float* pb1  = (const float*)d_in[29];
    const float* pW2  = (const float*)d_in[30];
    const float* pb2  = (const float*)d_in[31];
    float* out = (float*)d_out;

    const int* src = ei;
    const int* dst = ei + EE;

    float *h_ptr, *e_ptr, *agg_ptr, *u_ptr, *t_ptr;
    __nv_bfloat16 *wThi, *wTlo;
    cudaGetSymbolAddress((void**)&h_ptr,   g_h);
    cudaGetSymbolAddress((void**)&e_ptr,   g_e);
    cudaGetSymbolAddress((void**)&agg_ptr, g_agg);
    cudaGetSymbolAddress((void**)&u_ptr,   g_u);
    cudaGetSymbolAddress((void**)&t_ptr,   g_t);
    cudaGetSymbolAddress((void**)&wThi,    g_wThi);
    cudaGetSymbolAddress((void**)&wTlo,    g_wTlo);

    cudaFuncSetAttribute(mma_gemm<0>, cudaFuncAttributeMaxDynamicSharedMemorySize, MM_SMEM);
    cudaFuncSetAttribute(mma_gemm<2>, cudaFuncAttributeMaxDynamicSharedMemorySize, MM_SMEM);
    cudaFuncSetAttribute(mma_gemm<3>, cudaFuncAttributeMaxDynamicSharedMemorySize, MM_SMEM);

    dim3 thr(256);

    // weight transpose + bf16 split
    transp_split<<<dim3(8, 8, 12), dim3(32, 8)>>>(Wm, Wu);

    // input embeddings (ragged K, fp32 path)
    gemm_emb<<<dim3(2, NN / 128), thr>>>(nf, 69, 69, Wn, bn, h_ptr);
    gemm_emb<<<dim3(2, EE / 128), thr>>>(ef, 9, 9, We, be, e_ptr);

    // MPNN layers (mma.sync bf16x3, double-buffered + cp.async)
    for (int l = 0; l < LLAY; l++) {
        const __nv_bfloat16* topHi = wThi + (size_t)l * 65536;
        const __nv_bfloat16* topLo = wTlo + (size_t)l * 65536;
        const __nv_bfloat16* botHi = wThi + (size_t)(4 + l) * 65536;
        const __nv_bfloat16* botLo = wTlo + (size_t)(4 + l) * 65536;
        const __nv_bfloat16* wuHi  = wThi + (size_t)(8 + l) * 65536;
        const __nv_bfloat16* wuLo  = wTlo + (size_t)(8 + l) * 65536;

        cudaMemsetAsync(agg_ptr, 0, (size_t)NN * HIDD * sizeof(float), 0);

        // t = h @ Wm_top
        mma_gemm<2><<<dim3(2, NN / 128), thr, MM_SMEM>>>(
            h_ptr, topHi, topLo, nullptr, t_ptr, nullptr, nullptr, nullptr);

        // agg[dst] += relu(e @ Wm_bot + bm + t[src])
        mma_gemm<3><<<dim3(2, EE / 128), thr, MM_SMEM>>>(
            e_ptr, botHi, botLo, bm + (size_t)l * 256, agg_ptr, src, dst, t_ptr);

        // u = relu(agg @ Wu + bu)
        mma_gemm<0><<<dim3(2, NN / 128), thr, MM_SMEM>>>(
            agg_ptr, wuHi, wuLo, bu + (size_t)l * 256, u_ptr, nullptr, nullptr, nullptr);

        // h = LN(h + u)
        ln_kernel<<<NN / 8, 256>>>(u_ptr, lng + (size_t)l * 256, lnb + (size_t)l * 256);
    }

    // readout + FiLM + predictor
    seg_starts<<<NN / 256, 256>>>(bseg);
    readout_kernel<<<BBG, 256>>>();
    film_pred<<<BBG / 8, 256>>>(ctx, pid,
                                gW1, gb1, glng, glnb, gW2, gb2,
                                bW1, bb1, blng, blnb, bW2, bb2,
                                pW1, pb1, pW2, pb2, out);
}